// round 2
// baseline (speedup 1.0000x reference)
#include <cuda_runtime.h>
#include <math.h>
#include <stdint.h>

#define DIM 128
#define H 8
#define NMAX 100000
#define EMAX 1600000

// ---------------- device scratch (no allocations allowed) ----------------
__device__ float g_q[(size_t)NMAX * DIM];
__device__ float g_k[(size_t)NMAX * DIM];     // pre-scaled by 1/sqrt(HD)
__device__ float g_v[(size_t)NMAX * DIM];
__device__ float g_z[(size_t)NMAX * H];       // softmax denominators per dst/head
__device__ float g_agg[(size_t)NMAX * DIM];   // UNNORMALIZED weighted scatter-sum

// ---------------- zero scratch each launch (graph-replay safe) -----------
__global__ void zero_kernel(int n) {
    int stride = gridDim.x * blockDim.x;
    int i = blockIdx.x * blockDim.x + threadIdx.x;
    int total_agg = n * DIM;
    for (int j = i; j < total_agg; j += stride) g_agg[j] = 0.0f;
    int total_z = n * H;
    for (int j = i; j < total_z; j += stride) g_z[j] = 0.0f;
}

// ---------------- Y = (X @ W + b) * scale, X:[n,128], W:[128,128] --------
// which: 0->Y=g_q, 1->Y=g_k, 2->Y=g_v, 3->X=g_agg/g_z (normalized on load), Y=Yext
__global__ __launch_bounds__(256) void gemm128(
    const float* __restrict__ Xext, const float* __restrict__ W,
    const float* __restrict__ b, float* __restrict__ Yext,
    int which, int n, float scale)
{
    const float* X = (which == 3) ? g_agg : Xext;
    float* Y = (which == 0) ? g_q : (which == 1) ? g_k : (which == 2) ? g_v : Yext;

    __shared__ float xs[32][33];     // 32 rows x 32 k (padded)
    __shared__ float Ws[32][DIM];    // 32 k x 128 cols

    const int tid = threadIdx.x;
    const int cg = tid & 31;         // col group -> cols cg*4 .. cg*4+3 (lane)
    const int rg = tid >> 5;         // row group -> rows rg*4 .. rg*4+3 (warp id)
    const int row0 = blockIdx.x * 32;

    float acc[4][4];
#pragma unroll
    for (int i = 0; i < 4; i++)
#pragma unroll
        for (int j = 0; j < 4; j++) acc[i][j] = 0.0f;

    for (int kb = 0; kb < DIM; kb += 32) {
        // load x tile: 32 rows x 32 k = 1024 floats; thread t: row t/8, 4 floats
        {
            int r = tid >> 3;
            int kq = (tid & 7) * 4;
            int grow = row0 + r;
            float4 xv = make_float4(0.f, 0.f, 0.f, 0.f);
            if (grow < n) {
                xv = *(const float4*)&X[(size_t)grow * DIM + kb + kq];
                if (which == 3) {
                    // normalize by softmax denominator: 4 consecutive dims lie
                    // within one 16-dim head, so one z per float4
                    int h = (kb + kq) >> 4;
                    float zinv = 1.0f / g_z[(size_t)grow * H + h];
                    xv.x *= zinv; xv.y *= zinv; xv.z *= zinv; xv.w *= zinv;
                }
            }
            xs[r][kq + 0] = xv.x; xs[r][kq + 1] = xv.y;
            xs[r][kq + 2] = xv.z; xs[r][kq + 3] = xv.w;
        }
        // load W tile: rows kb..kb+31, all 128 cols = 1024 float4s
        {
            const float4* Wg = (const float4*)&W[(size_t)kb * DIM];
            float4* Wsv = (float4*)&Ws[0][0];
#pragma unroll
            for (int i = 0; i < 4; i++) Wsv[tid + i * 256] = Wg[tid + i * 256];
        }
        __syncthreads();

#pragma unroll
        for (int kk = 0; kk < 32; kk++) {
            float4 wv = *(const float4*)&Ws[kk][cg * 4];
            float x0 = xs[rg * 4 + 0][kk];
            float x1 = xs[rg * 4 + 1][kk];
            float x2 = xs[rg * 4 + 2][kk];
            float x3 = xs[rg * 4 + 3][kk];
            acc[0][0] += x0 * wv.x; acc[0][1] += x0 * wv.y; acc[0][2] += x0 * wv.z; acc[0][3] += x0 * wv.w;
            acc[1][0] += x1 * wv.x; acc[1][1] += x1 * wv.y; acc[1][2] += x1 * wv.z; acc[1][3] += x1 * wv.w;
            acc[2][0] += x2 * wv.x; acc[2][1] += x2 * wv.y; acc[2][2] += x2 * wv.z; acc[2][3] += x2 * wv.w;
            acc[3][0] += x3 * wv.x; acc[3][1] += x3 * wv.y; acc[3][2] += x3 * wv.z; acc[3][3] += x3 * wv.w;
        }
        __syncthreads();
    }

    float4 bv = *(const float4*)&b[cg * 4];
#pragma unroll
    for (int i = 0; i < 4; i++) {
        int grow = row0 + rg * 4 + i;
        if (grow < n) {
            float4 o;
            o.x = (acc[i][0] + bv.x) * scale;
            o.y = (acc[i][1] + bv.y) * scale;
            o.z = (acc[i][2] + bv.z) * scale;
            o.w = (acc[i][3] + bv.w) * scale;
            *(float4*)&Y[(size_t)grow * DIM + cg * 4] = o;
        }
    }
}

// ---------------- fused edge pass ----------------------------------------
// one warp per edge; lane handles 4 of 128 dims; head = lane>>2
//   w = exp(q[src].k[dst])        (k pre-scaled by 1/sqrt(HD))
//   z[dst]   += w                 (per head)
//   agg[dst] += v[src] * w        (unnormalized; divided by z in output GEMM)
__global__ __launch_bounds__(256) void edge_fused(
    const int* __restrict__ src, const int* __restrict__ dst, int E)
{
    int e = (int)((blockIdx.x * blockDim.x + threadIdx.x) >> 5);
    int lane = threadIdx.x & 31;
    if (e >= E) return;
    int s = src[e];
    int d = dst[e];
    float4 qv = *(const float4*)&g_q[(size_t)s * DIM + lane * 4];
    float4 kv = *(const float4*)&g_k[(size_t)d * DIM + lane * 4];
    float p = qv.x * kv.x + qv.y * kv.y + qv.z * kv.z + qv.w * kv.w;
    p += __shfl_xor_sync(0xffffffffu, p, 1);
    p += __shfl_xor_sync(0xffffffffu, p, 2);
    // after the 2 shfls, all 4 lanes of each head group hold the head's dot.
    // scores ~N(0,1): exp without max-subtraction cannot overflow fp32.
    float w = __expf(p);
    if ((lane & 3) == 0)
        atomicAdd(&g_z[(size_t)d * H + (lane >> 2)], w);
    float4 vv = *(const float4*)&g_v[(size_t)s * DIM + lane * 4];
    float* pa = &g_agg[(size_t)d * DIM + lane * 4];
    asm volatile("red.global.add.v4.f32 [%0], {%1, %2, %3, %4};"
                 :: "l"(pa), "f"(vv.x * w), "f"(vv.y * w), "f"(vv.z * w), "f"(vv.w * w)
                 : "memory");
}

// ---------------- host entry ----------------------------------------------
extern "C" void kernel_launch(void* const* d_in, const int* in_sizes, int n_in,
                              void* d_out, int out_size)
{
    const float* x   = (const float*)d_in[0];
    const int*   src = (const int*)d_in[1];
    const int*   dst = (const int*)d_in[2];
    const float* Wq  = (const float*)d_in[3];
    const float* bq  = (const float*)d_in[4];
    const float* Wk  = (const float*)d_in[5];
    const float* bk  = (const float*)d_in[6];
    const float* Wv  = (const float*)d_in[7];
    const float* bv  = (const float*)d_in[8];
    const float* Wo  = (const float*)d_in[9];
    const float* bo  = (const float*)d_in[10];
    float* out = (float*)d_out;

    int n = in_sizes[0] / DIM;
    int E = in_sizes[1];

    zero_kernel<<<1184, 256>>>(n);

    dim3 gb((n + 31) / 32);
    const float inv_sqrt_hd = 0.25f;  // 1/sqrt(16)
    gemm128<<<gb, 256>>>(x, Wq, bq, nullptr, 0, n, 1.0f);
    gemm128<<<gb, 256>>>(x, Wk, bk, nullptr, 1, n, inv_sqrt_hd);
    gemm128<<<gb, 256>>>(x, Wv, bv, nullptr, 2, n, 1.0f);

    int eb = (E + 7) / 8;  // 8 warps per block, 1 edge per warp
    edge_fused<<<eb, 256>>>(src, dst, E);

    gemm128<<<gb, 256>>>(nullptr, Wo, bo, out, 3, n, 1.0f);
}

// round 3
// speedup vs baseline: 1.3932x; 1.3932x over previous
#include <cuda_runtime.h>
#include <math.h>
#include <stdint.h>

#define DIM 128
#define H 8
#define NMAX 100000
#define EMAX 1600000
#define NB_MAX 512            // blocks of 256 covering NMAX (391 used)

// ---------------- device scratch (no allocations allowed) ----------------
__device__ float g_q[(size_t)NMAX * DIM];
__device__ float g_k[(size_t)NMAX * DIM];     // pre-scaled by 1/sqrt(HD)
__device__ float g_v[(size_t)NMAX * DIM];
__device__ float g_agg[(size_t)NMAX * DIM];   // NORMALIZED weighted sums
__device__ int   g_cnt[NMAX];                 // per-dst degree
__device__ int   g_fill[NMAX];                // scatter cursors
__device__ int   g_start[NMAX];               // exclusive prefix of cnt
__device__ int   g_bsum[NB_MAX];              // per-block sums
__device__ int   g_boff[NB_MAX];              // exclusive prefix of bsum
__device__ int   g_esrc[EMAX];                // src ids sorted by dst

// ---------------- sort pipeline ------------------------------------------
__global__ void zero_counts(int n) {
    int i = blockIdx.x * blockDim.x + threadIdx.x;
    int stride = gridDim.x * blockDim.x;
    for (int j = i; j < n; j += stride) { g_cnt[j] = 0; g_fill[j] = 0; }
}

__global__ void hist_kernel(const int* __restrict__ dst, int E) {
    int i = blockIdx.x * blockDim.x + threadIdx.x;
    int stride = gridDim.x * blockDim.x;
    for (int e = i; e < E; e += stride) atomicAdd(&g_cnt[dst[e]], 1);
}

// per-256-block exclusive scan of g_cnt -> g_start (local), totals -> g_bsum
__global__ __launch_bounds__(256) void scan_blocks(int n) {
    __shared__ int s[256];
    int t = threadIdx.x;
    int gi = blockIdx.x * 256 + t;
    int v = (gi < n) ? g_cnt[gi] : 0;
    s[t] = v;
    __syncthreads();
    // Hillis-Steele inclusive
#pragma unroll
    for (int off = 1; off < 256; off <<= 1) {
        int tmp = (t >= off) ? s[t - off] : 0;
        __syncthreads();
        s[t] += tmp;
        __syncthreads();
    }
    if (gi < n) g_start[gi] = s[t] - v;          // exclusive
    if (t == 255) g_bsum[blockIdx.x] = s[255];
}

__global__ __launch_bounds__(NB_MAX) void scan_bsums(int nb) {
    __shared__ int s[NB_MAX];
    int t = threadIdx.x;
    int v = (t < nb) ? g_bsum[t] : 0;
    s[t] = v;
    __syncthreads();
#pragma unroll
    for (int off = 1; off < NB_MAX; off <<= 1) {
        int tmp = (t >= off) ? s[t - off] : 0;
        __syncthreads();
        s[t] += tmp;
        __syncthreads();
    }
    if (t < nb) g_boff[t] = s[t] - v;            // exclusive
}

__global__ void add_offsets(int n) {
    int i = blockIdx.x * blockDim.x + threadIdx.x;
    int stride = gridDim.x * blockDim.x;
    for (int j = i; j < n; j += stride) g_start[j] += g_boff[j >> 8];
}

__global__ void scatter_kernel(const int* __restrict__ src,
                               const int* __restrict__ dst, int E) {
    int i = blockIdx.x * blockDim.x + threadIdx.x;
    int stride = gridDim.x * blockDim.x;
    for (int e = i; e < E; e += stride) {
        int d = dst[e];
        int pos = g_start[d] + atomicAdd(&g_fill[d], 1);
        g_esrc[pos] = src[e];
    }
}

// ---------------- Y = (X @ W + b) * scale, X:[n,128], W:[128,128] --------
// which: 0->Y=g_q, 1->Y=g_k, 2->Y=g_v, 3->X=g_agg, Y=Yext
__global__ __launch_bounds__(256) void gemm128(
    const float* __restrict__ Xext, const float* __restrict__ W,
    const float* __restrict__ b, float* __restrict__ Yext,
    int which, int n, float scale)
{
    const float* X = (which == 3) ? g_agg : Xext;
    float* Y = (which == 0) ? g_q : (which == 1) ? g_k : (which == 2) ? g_v : Yext;

    __shared__ float xs[32][36];     // 32 rows x 32 k, padded to 36 (16B-aligned rows)
    __shared__ float Ws[32][DIM];    // 32 k x 128 cols

    const int tid = threadIdx.x;
    const int cg = tid & 31;         // cols cg*4 .. cg*4+3
    const int rg = tid >> 5;         // rows rg*4 .. rg*4+3
    const int row0 = blockIdx.x * 32;

    float acc[4][4];
#pragma unroll
    for (int i = 0; i < 4; i++)
#pragma unroll
        for (int j = 0; j < 4; j++) acc[i][j] = 0.0f;

    for (int kb = 0; kb < DIM; kb += 32) {
        {
            int r = tid >> 3;
            int kq = (tid & 7) * 4;
            int grow = row0 + r;
            float4 xv = make_float4(0.f, 0.f, 0.f, 0.f);
            if (grow < n) xv = *(const float4*)&X[(size_t)grow * DIM + kb + kq];
            *(float4*)&xs[r][kq] = xv;
        }
        {
            const float4* Wg = (const float4*)&W[(size_t)kb * DIM];
            float4* Wsv = (float4*)&Ws[0][0];
#pragma unroll
            for (int i = 0; i < 4; i++) Wsv[tid + i * 256] = Wg[tid + i * 256];
        }
        __syncthreads();

#pragma unroll
        for (int kk4 = 0; kk4 < 8; kk4++) {
            // one broadcast LDS.128 per row instead of 4 scalar LDS
            float4 xv0 = *(const float4*)&xs[rg * 4 + 0][kk4 * 4];
            float4 xv1 = *(const float4*)&xs[rg * 4 + 1][kk4 * 4];
            float4 xv2 = *(const float4*)&xs[rg * 4 + 2][kk4 * 4];
            float4 xv3 = *(const float4*)&xs[rg * 4 + 3][kk4 * 4];
            const float* x0 = (const float*)&xv0;
            const float* x1 = (const float*)&xv1;
            const float* x2 = (const float*)&xv2;
            const float* x3 = (const float*)&xv3;
#pragma unroll
            for (int j = 0; j < 4; j++) {
                float4 wv = *(const float4*)&Ws[kk4 * 4 + j][cg * 4];
                acc[0][0] += x0[j] * wv.x; acc[0][1] += x0[j] * wv.y;
                acc[0][2] += x0[j] * wv.z; acc[0][3] += x0[j] * wv.w;
                acc[1][0] += x1[j] * wv.x; acc[1][1] += x1[j] * wv.y;
                acc[1][2] += x1[j] * wv.z; acc[1][3] += x1[j] * wv.w;
                acc[2][0] += x2[j] * wv.x; acc[2][1] += x2[j] * wv.y;
                acc[2][2] += x2[j] * wv.z; acc[2][3] += x2[j] * wv.w;
                acc[3][0] += x3[j] * wv.x; acc[3][1] += x3[j] * wv.y;
                acc[3][2] += x3[j] * wv.z; acc[3][3] += x3[j] * wv.w;
            }
        }
        __syncthreads();
    }

    float4 bv = *(const float4*)&b[cg * 4];
#pragma unroll
    for (int i = 0; i < 4; i++) {
        int grow = row0 + rg * 4 + i;
        if (grow < n) {
            float4 o;
            o.x = (acc[i][0] + bv.x) * scale;
            o.y = (acc[i][1] + bv.y) * scale;
            o.z = (acc[i][2] + bv.z) * scale;
            o.w = (acc[i][3] + bv.w) * scale;
            *(float4*)&Y[(size_t)grow * DIM + cg * 4] = o;
        }
    }
}

// ---------------- edge pass: warp per destination node -------------------
// Edges pre-sorted by dst (g_esrc). Per node d:
//   for each incoming edge (src s): w = exp(q[s].k[d]); agg += w*v[s]; z += w
//   g_agg[d] = agg / z   (plain stores, no atomics)
__global__ __launch_bounds__(256) void edge_sorted(int n) {
    int d = (int)((blockIdx.x * blockDim.x + threadIdx.x) >> 5);
    int lane = threadIdx.x & 31;
    if (d >= n) return;

    int base = g_start[d];
    int deg  = g_cnt[d];

    float4 kv = *(const float4*)&g_k[(size_t)d * DIM + lane * 4];
    float4 agg = make_float4(0.f, 0.f, 0.f, 0.f);
    float zacc = 0.0f;

    for (int chunk = 0; chunk < deg; chunk += 32) {
        int nmax = min(32, deg - chunk);
        int sv = (chunk + lane < deg) ? g_esrc[base + chunk + lane] : 0;
#pragma unroll 2
        for (int t = 0; t < nmax; t++) {
            int s = __shfl_sync(0xffffffffu, sv, t);
            float4 qv = *(const float4*)&g_q[(size_t)s * DIM + lane * 4];
            float p = qv.x * kv.x + qv.y * kv.y + qv.z * kv.z + qv.w * kv.w;
            p += __shfl_xor_sync(0xffffffffu, p, 1);
            p += __shfl_xor_sync(0xffffffffu, p, 2);
            // k pre-scaled by 1/sqrt(HD); scores ~N(0,1): exp cannot overflow
            float w = __expf(p);
            float4 vv = *(const float4*)&g_v[(size_t)s * DIM + lane * 4];
            agg.x += w * vv.x; agg.y += w * vv.y;
            agg.z += w * vv.z; agg.w += w * vv.w;
            zacc += w;
        }
    }

    float4 o = make_float4(0.f, 0.f, 0.f, 0.f);
    if (deg > 0) {
        float zinv = 1.0f / zacc;
        o.x = agg.x * zinv; o.y = agg.y * zinv;
        o.z = agg.z * zinv; o.w = agg.w * zinv;
    }
    *(float4*)&g_agg[(size_t)d * DIM + lane * 4] = o;
}

// ---------------- host entry ----------------------------------------------
extern "C" void kernel_launch(void* const* d_in, const int* in_sizes, int n_in,
                              void* d_out, int out_size)
{
    const float* x   = (const float*)d_in[0];
    const int*   src = (const int*)d_in[1];
    const int*   dst = (const int*)d_in[2];
    const float* Wq  = (const float*)d_in[3];
    const float* bq  = (const float*)d_in[4];
    const float* Wk  = (const float*)d_in[5];
    const float* bk  = (const float*)d_in[6];
    const float* Wv  = (const float*)d_in[7];
    const float* bv  = (const float*)d_in[8];
    const float* Wo  = (const float*)d_in[9];
    const float* bo  = (const float*)d_in[10];
    float* out = (float*)d_out;

    int n = in_sizes[0] / DIM;
    int E = in_sizes[1];
    int nb = (n + 255) / 256;

    // --- counting sort of edges by dst ---
    zero_counts<<<256, 256>>>(n);
    hist_kernel<<<1024, 256>>>(dst, E);
    scan_blocks<<<nb, 256>>>(n);
    scan_bsums<<<1, NB_MAX>>>(nb);
    add_offsets<<<256, 256>>>(n);
    scatter_kernel<<<1024, 256>>>(src, dst, E);

    // --- q/k/v projections ---
    dim3 gb((n + 31) / 32);
    const float inv_sqrt_hd = 0.25f;  // 1/sqrt(16)
    gemm128<<<gb, 256>>>(x, Wq, bq, nullptr, 0, n, 1.0f);
    gemm128<<<gb, 256>>>(x, Wk, bk, nullptr, 1, n, inv_sqrt_hd);
    gemm128<<<gb, 256>>>(x, Wv, bv, nullptr, 2, n, 1.0f);

    // --- fused attention (gather + softmax + aggregate, no atomics) ---
    edge_sorted<<<(n + 7) / 8, 256>>>(n);

    // --- output projection ---
    gemm128<<<gb, 256>>>(nullptr, Wo, bo, out, 3, n, 1.0f);
}

// round 7
// speedup vs baseline: 1.6357x; 1.1740x over previous
#include <cuda_runtime.h>
#include <cuda_bf16.h>
#include <math.h>
#include <stdint.h>

#define DIM 128
#define H 8
#define NMAX 100000
#define EMAX 1600000
#define NB_MAX 512
#define ASTR 136                       // padded SMEM row stride (elements)

// ---------------- device scratch (no allocations allowed) ----------------
__device__ float g_q[(size_t)NMAX * DIM];
__device__ float g_k[(size_t)NMAX * DIM];     // pre-scaled by 1/sqrt(HD)
__device__ float g_v[(size_t)NMAX * DIM];
__device__ float g_agg[(size_t)NMAX * DIM];   // NORMALIZED weighted sums
__device__ int   g_cnt[NMAX];
__device__ int   g_fill[NMAX];
__device__ int   g_start[NMAX];
__device__ int   g_bsum[NB_MAX];
__device__ int   g_boff[NB_MAX];
__device__ int   g_esrc[EMAX];
// W^T split into bf16 hi/lo, row-major [nout][k], 4 matrices
__device__ uint4 g_bhi[4 * 2048];
__device__ uint4 g_blo[4 * 2048];

// ---------------- helpers -------------------------------------------------
__device__ __forceinline__ uint32_t smem_u32(const void* p) {
    uint32_t a;
    asm("{ .reg .u64 t; cvta.to.shared.u64 t, %1; cvt.u32.u64 %0, t; }" : "=r"(a) : "l"(p));
    return a;
}

__device__ __forceinline__ void pack8(const float* f, uint4& hi, uint4& lo) {
    uint32_t hu[4], lu[4];
#pragma unroll
    for (int i = 0; i < 4; i++) {
        __nv_bfloat16 h0 = __float2bfloat16(f[2 * i]);
        __nv_bfloat16 h1 = __float2bfloat16(f[2 * i + 1]);
        float l0 = f[2 * i] - __bfloat162float(h0);      // exact (Sterbenz)
        float l1 = f[2 * i + 1] - __bfloat162float(h1);
        __nv_bfloat162 hp = __halves2bfloat162(h0, h1);
        __nv_bfloat162 lp = __halves2bfloat162(__float2bfloat16(l0), __float2bfloat16(l1));
        hu[i] = *(uint32_t*)&hp;
        lu[i] = *(uint32_t*)&lp;
    }
    hi = make_uint4(hu[0], hu[1], hu[2], hu[3]);
    lo = make_uint4(lu[0], lu[1], lu[2], lu[3]);
}

__device__ __forceinline__ void ldm4(uint32_t* r, uint32_t addr) {
    asm volatile("ldmatrix.sync.aligned.m8n8.x4.shared.b16 {%0,%1,%2,%3}, [%4];"
                 : "=r"(r[0]), "=r"(r[1]), "=r"(r[2]), "=r"(r[3]) : "r"(addr));
}

__device__ __forceinline__ void mma16816(float* d, const uint32_t* a, uint32_t b0, uint32_t b1) {
    asm volatile(
        "mma.sync.aligned.m16n8k16.row.col.f32.bf16.bf16.f32 "
        "{%0,%1,%2,%3}, {%4,%5,%6,%7}, {%8,%9}, {%0,%1,%2,%3};"
        : "+f"(d[0]), "+f"(d[1]), "+f"(d[2]), "+f"(d[3])
        : "r"(a[0]), "r"(a[1]), "r"(a[2]), "r"(a[3]), "r"(b0), "r"(b1));
}

// ---------------- W conversion: W[k][n] fp32 -> Wt[n][k] bf16 hi/lo -------
__global__ __launch_bounds__(256) void conv_w(
    const float* __restrict__ Wq, const float* __restrict__ Wk,
    const float* __restrict__ Wv, const float* __restrict__ Wo)
{
    const float* W = (blockIdx.x == 0) ? Wq : (blockIdx.x == 1) ? Wk
                    : (blockIdx.x == 2) ? Wv : Wo;
    int t = threadIdx.x;
    int nr = t >> 1, half = t & 1;
#pragma unroll
    for (int j = 0; j < 8; j++) {
        int col8 = half * 8 + j;   // k-group (8 k's)
        int k0 = col8 * 8;
        float f[8];
#pragma unroll
        for (int i = 0; i < 8; i++) f[i] = W[(size_t)(k0 + i) * DIM + nr];
        uint4 hi, lo;
        pack8(f, hi, lo);
        g_bhi[blockIdx.x * 2048 + nr * 16 + col8] = hi;
        g_blo[blockIdx.x * 2048 + nr * 16 + col8] = lo;
    }
}

// ---------------- tensor-core GEMM: Y = (X @ W + b) * scale ---------------
// split-bf16 via mma.sync: D = Ah*Bh + Ah*Bl + Al*Bh (fp32 accumulate)
// CTA: 128 rows x 128 cols, 8 warps in 4x2, warp tile 32x64
#define SM_BYTES (4 * 128 * ASTR * 2)

__global__ __launch_bounds__(256) void hmma_gemm(
    const float* __restrict__ Xext, const float* __restrict__ bias,
    float* __restrict__ Yext, int which, int n, float scale)
{
    extern __shared__ __align__(16) char smem[];
    __nv_bfloat16* Ah = (__nv_bfloat16*)smem;            // [128][ASTR]
    __nv_bfloat16* Al = Ah + 128 * ASTR;
    __nv_bfloat16* Bh = Al + 128 * ASTR;                 // Wt rows = n, cols = k
    __nv_bfloat16* Bl = Bh + 128 * ASTR;
    const uint32_t HL_OFF = 128 * ASTR * 2;              // hi -> lo byte offset

    const float* X = (which == 3) ? g_agg : Xext;
    float* Y = (which == 0) ? g_q : (which == 1) ? g_k : (which == 2) ? g_v : Yext;

    int tid = threadIdx.x;
    int row0 = blockIdx.x * 128;

    // ---- stage A: load fp32 X tile, split to bf16 hi/lo in SMEM ----
    {
        int r = tid >> 1, half = tid & 1;
        int grow = row0 + r;
#pragma unroll
        for (int j = 0; j < 8; j++) {
            int c0 = half * 64 + j * 8;
            float f[8] = {0, 0, 0, 0, 0, 0, 0, 0};
            if (grow < n) {
                float4 a = *(const float4*)&X[(size_t)grow * DIM + c0];
                float4 b = *(const float4*)&X[(size_t)grow * DIM + c0 + 4];
                f[0] = a.x; f[1] = a.y; f[2] = a.z; f[3] = a.w;
                f[4] = b.x; f[5] = b.y; f[6] = b.z; f[7] = b.w;
            }
            uint4 hi, lo;
            pack8(f, hi, lo);
            *(uint4*)&Ah[r * ASTR + c0] = hi;
            *(uint4*)&Al[r * ASTR + c0] = lo;
        }
    }
    // ---- stage B: copy pre-split Wt from global ----
    {
        const uint4* bh = g_bhi + which * 2048;
        const uint4* bl = g_blo + which * 2048;
#pragma unroll
        for (int i = 0; i < 8; i++) {
            int idx = tid * 8 + i;            // 0..2047
            int nrow = idx >> 4, c8 = idx & 15;
            *(uint4*)&Bh[nrow * ASTR + c8 * 8] = bh[idx];
            *(uint4*)&Bl[nrow * ASTR + c8 * 8] = bl[idx];
        }
    }
    __syncthreads();

    int wid = tid >> 5, lane = tid & 31;
    int wm = wid & 3, wn = wid >> 2;          // 4x2 warp grid

    float acc[2][8][4];
#pragma unroll
    for (int mt = 0; mt < 2; mt++)
#pragma unroll
        for (int nt = 0; nt < 8; nt++)
#pragma unroll
            for (int i = 0; i < 4; i++) acc[mt][nt][i] = 0.0f;

    uint32_t aBase = smem_u32(Ah);
    uint32_t bBase = smem_u32(Bh);

#pragma unroll
    for (int ks = 0; ks < 8; ks++) {
        // A fragments (16x16 per mtile): lane l -> &A[wm*32+mt*16 + l%16][ks*16 + (l/16)*8]
        uint32_t a_h[2][4], a_l[2][4];
#pragma unroll
        for (int mt = 0; mt < 2; mt++) {
            int arow = wm * 32 + mt * 16 + (lane & 15);
            int acol = ks * 16 + (lane >> 4) * 8;
            uint32_t ad = aBase + (uint32_t)(arow * ASTR + acol) * 2;
            ldm4(a_h[mt], ad);
            ldm4(a_l[mt], ad + HL_OFF);
        }
        // B fragments: x4 covers 2 ntiles; lane l -> row wn*64+np*16+(l/16)*8+(l&7),
        // col ks*16 + ((l>>3)&1)*8
        uint32_t b_h[4][4], b_l[4][4];
#pragma unroll
        for (int np = 0; np < 4; np++) {
            int brow = wn * 64 + np * 16 + (lane >> 4) * 8 + (lane & 7);
            int bcol = ks * 16 + ((lane >> 3) & 1) * 8;
            uint32_t bd = bBase + (uint32_t)(brow * ASTR + bcol) * 2;
            ldm4(b_h[np], bd);
            ldm4(b_l[np], bd + HL_OFF);
        }
#pragma unroll
        for (int mt = 0; mt < 2; mt++)
#pragma unroll
            for (int nt = 0; nt < 8; nt++) {
                int np = nt >> 1, sel = (nt & 1) * 2;
                mma16816(acc[mt][nt], a_h[mt], b_h[np][sel], b_h[np][sel + 1]);
                mma16816(acc[mt][nt], a_h[mt], b_l[np][sel], b_l[np][sel + 1]);
                mma16816(acc[mt][nt], a_l[mt], b_h[np][sel], b_h[np][sel + 1]);
            }
    }

    // ---- epilogue: d0,d1 -> row base + l/4, cols +0,1; d2,d3 -> row +8 ----
#pragma unroll
    for (int mt = 0; mt < 2; mt++) {
        int rbase = row0 + wm * 32 + mt * 16 + (lane >> 2);
#pragma unroll
        for (int nt = 0; nt < 8; nt++) {
            int col = wn * 64 + nt * 8 + (lane & 3) * 2;
            float2 bv = *(const float2*)&bias[col];
            if (rbase < n) {
                float2 o0;
                o0.x = (acc[mt][nt][0] + bv.x) * scale;
                o0.y = (acc[mt][nt][1] + bv.y) * scale;
                *(float2*)&Y[(size_t)rbase * DIM + col] = o0;
            }
            if (rbase + 8 < n) {
                float2 o1;
                o1.x = (acc[mt][nt][2] + bv.x) * scale;
                o1.y = (acc[mt][nt][3] + bv.y) * scale;
                *(float2*)&Y[(size_t)(rbase + 8) * DIM + col] = o1;
            }
        }
    }
}

// ---------------- counting sort of edges by dst ---------------------------
__global__ void zero_counts(int n) {
    int i = blockIdx.x * blockDim.x + threadIdx.x;
    int stride = gridDim.x * blockDim.x;
    for (int j = i; j < n; j += stride) { g_cnt[j] = 0; g_fill[j] = 0; }
}

__global__ void hist_kernel(const int* __restrict__ dst, int E) {
    int i = blockIdx.x * blockDim.x + threadIdx.x;
    int stride = gridDim.x * blockDim.x;
    for (int e = i; e < E; e += stride) atomicAdd(&g_cnt[dst[e]], 1);
}

__global__ __launch_bounds__(256) void scan_blocks(int n) {
    __shared__ int s[256];
    int t = threadIdx.x;
    int gi = blockIdx.x * 256 + t;
    int v = (gi < n) ? g_cnt[gi] : 0;
    s[t] = v;
    __syncthreads();
#pragma unroll
    for (int off = 1; off < 256; off <<= 1) {
        int tmp = (t >= off) ? s[t - off] : 0;
        __syncthreads();
        s[t] += tmp;
        __syncthreads();
    }
    if (gi < n) g_start[gi] = s[t] - v;
    if (t == 255) g_bsum[blockIdx.x] = s[255];
}

__global__ __launch_bounds__(NB_MAX) void scan_bsums(int nb) {
    __shared__ int s[NB_MAX];
    int t = threadIdx.x;
    int v = (t < nb) ? g_bsum[t] : 0;
    s[t] = v;
    __syncthreads();
#pragma unroll
    for (int off = 1; off < NB_MAX; off <<= 1) {
        int tmp = (t >= off) ? s[t - off] : 0;
        __syncthreads();
        s[t] += tmp;
        __syncthreads();
    }
    if (t < nb) g_boff[t] = s[t] - v;
}

__global__ void add_offsets(int n) {
    int i = blockIdx.x * blockDim.x + threadIdx.x;
    int stride = gridDim.x * blockDim.x;
    for (int j = i; j < n; j += stride) g_start[j] += g_boff[j >> 8];
}

__global__ void scatter_kernel(const int* __restrict__ src,
                               const int* __restrict__ dst, int E) {
    int i = blockIdx.x * blockDim.x + threadIdx.x;
    int stride = gridDim.x * blockDim.x;
    for (int e = i; e < E; e += stride) {
        int d = dst[e];
        int pos = g_start[d] + atomicAdd(&g_fill[d], 1);
        g_esrc[pos] = src[e];
    }
}

// ---------------- attention: warp per destination node --------------------
__global__ __launch_bounds__(256) void edge_sorted(int n) {
    int d = (int)((blockIdx.x * blockDim.x + threadIdx.x) >> 5);
    int lane = threadIdx.x & 31;
    if (d >= n) return;

    int base = g_start[d];
    int deg  = g_cnt[d];

    float4 kv = *(const float4*)&g_k[(size_t)d * DIM + lane * 4];
    float4 agg = make_float4(0.f, 0.f, 0.f, 0.f);
    float zacc = 0.0f;

    for (int chunk = 0; chunk < deg; chunk += 32) {
        int nmax = min(32, deg - chunk);
        int sv = (chunk + lane < deg) ? g_esrc[base + chunk + lane] : 0;
#pragma unroll 2
        for (int t = 0; t < nmax; t++) {
            int s = __shfl_sync(0xffffffffu, sv, t);
            float4 qv = *(const float4*)&g_q[(size_t)s * DIM + lane * 4];
            float p = qv.x * kv.x + qv.y * kv.y + qv.z * kv.z + qv.w * kv.w;
            p += __shfl_xor_sync(0xffffffffu, p, 1);
            p += __shfl_xor_sync(0xffffffffu, p, 2);
            float w = __expf(p);   // k pre-scaled; scores ~N(0,1), no overflow
            float4 vv = *(const float4*)&g_v[(size_t)s * DIM + lane * 4];
            agg.x += w * vv.x; agg.y += w * vv.y;
            agg.z += w * vv.z; agg.w += w * vv.w;
            zacc += w;
        }
    }

    float4 o = make_float4(0.f, 0.f, 0.f, 0.f);
    if (deg > 0) {
        float zinv = 1.0f / zacc;
        o.x = agg.x * zinv; o.y = agg.y * zinv;
        o.z = agg.z * zinv; o.w = agg.w * zinv;
    }
    *(float4*)&g_agg[(size_t)d * DIM + lane * 4] = o;
}

// ---------------- host entry ----------------------------------------------
extern "C" void kernel_launch(void* const* d_in, const int* in_sizes, int n_in,
                              void* d_out, int out_size)
{
    const float* x   = (const float*)d_in[0];
    const int*   src = (const int*)d_in[1];
    const int*   dst = (const int*)d_in[2];
    const float* Wq  = (const float*)d_in[3];
    const float* bq  = (const float*)d_in[4];
    const float* Wk  = (const float*)d_in[5];
    const float* bk  = (const float*)d_in[6];
    const float* Wv  = (const float*)d_in[7];
    const float* bv  = (const float*)d_in[8];
    const float* Wo  = (const float*)d_in[9];
    const float* bo  = (const float*)d_in[10];
    float* out = (float*)d_out;

    int n = in_sizes[0] / DIM;
    int E = in_sizes[1];
    int nb = (n + 255) / 256;
    int tiles = (n + 127) / 128;

    cudaFuncSetAttribute(hmma_gemm, cudaFuncAttributeMaxDynamicSharedMemorySize, SM_BYTES);

    const float inv_sqrt_hd = 0.25f;  // 1/sqrt(16)

    // W conversion + q/k/v projections (tensor cores via mma.sync)
    conv_w<<<4, 256>>>(Wq, Wk, Wv, Wo);
    hmma_gemm<<<tiles, 256, SM_BYTES>>>(x, bq, nullptr, 0, n, 1.0f);
    hmma_gemm<<<tiles, 256, SM_BYTES>>>(x, bk, nullptr, 1, n, inv_sqrt_hd);
    hmma_gemm<<<tiles, 256, SM_BYTES>>>(x, bv, nullptr, 2, n, 1.0f);

    // counting sort of edges by dst
    zero_counts<<<256, 256>>>(n);
    hist_kernel<<<1024, 256>>>(dst, E);
    scan_blocks<<<nb, 256>>>(n);
    scan_bsums<<<1, NB_MAX>>>(nb);
    add_offsets<<<256, 256>>>(n);
    scatter_kernel<<<1024, 256>>>(src, dst, E);

    // fused attention (gather + softmax + aggregate, no atomics)
    edge_sorted<<<(n + 7) / 8, 256>>>(n);

    // output projection
    hmma_gemm<<<tiles, 256, SM_BYTES>>>(nullptr, bo, out, 3, n, 1.0f);
}

// round 8
// speedup vs baseline: 1.8961x; 1.1592x over previous
#include <cuda_runtime.h>
#include <cuda_bf16.h>
#include <math.h>
#include <stdint.h>

#define DIM 128
#define H 8
#define NMAX 100000
#define EMAX 1600000
#define NB_MAX 512
#define ASTR 136                       // padded SMEM row stride (elements)

// ---------------- device scratch (no allocations allowed) ----------------
__device__ float g_q[(size_t)NMAX * DIM];
__device__ float g_k[(size_t)NMAX * DIM];     // pre-scaled by 1/sqrt(HD)
__device__ float g_v[(size_t)NMAX * DIM];
__device__ float g_agg[(size_t)NMAX * DIM];   // NORMALIZED weighted sums
__device__ int   g_cnt[NMAX];
__device__ int   g_fill[NMAX];
__device__ int   g_start[NMAX];
__device__ int   g_bsum[NB_MAX];
__device__ int   g_boff[NB_MAX];
__device__ int   g_esrc[EMAX];
// W^T split into bf16 hi/lo, row-major [nout][k], 4 matrices
__device__ uint4 g_bhi[4 * 2048];
__device__ uint4 g_blo[4 * 2048];

// ---------------- helpers -------------------------------------------------
__device__ __forceinline__ uint32_t smem_u32(const void* p) {
    uint32_t a;
    asm("{ .reg .u64 t; cvta.to.shared.u64 t, %1; cvt.u32.u64 %0, t; }" : "=r"(a) : "l"(p));
    return a;
}

__device__ __forceinline__ void pack8(const float* f, uint4& hi, uint4& lo) {
    uint32_t hu[4], lu[4];
#pragma unroll
    for (int i = 0; i < 4; i++) {
        __nv_bfloat16 h0 = __float2bfloat16(f[2 * i]);
        __nv_bfloat16 h1 = __float2bfloat16(f[2 * i + 1]);
        float l0 = f[2 * i] - __bfloat162float(h0);      // exact (Sterbenz)
        float l1 = f[2 * i + 1] - __bfloat162float(h1);
        __nv_bfloat162 hp = __halves2bfloat162(h0, h1);
        __nv_bfloat162 lp = __halves2bfloat162(__float2bfloat16(l0), __float2bfloat16(l1));
        hu[i] = *(uint32_t*)&hp;
        lu[i] = *(uint32_t*)&lp;
    }
    hi = make_uint4(hu[0], hu[1], hu[2], hu[3]);
    lo = make_uint4(lu[0], lu[1], lu[2], lu[3]);
}

__device__ __forceinline__ void ldm4(uint32_t* r, uint32_t addr) {
    asm volatile("ldmatrix.sync.aligned.m8n8.x4.shared.b16 {%0,%1,%2,%3}, [%4];"
                 : "=r"(r[0]), "=r"(r[1]), "=r"(r[2]), "=r"(r[3]) : "r"(addr));
}

__device__ __forceinline__ void mma16816(float* d, const uint32_t* a, uint32_t b0, uint32_t b1) {
    asm volatile(
        "mma.sync.aligned.m16n8k16.row.col.f32.bf16.bf16.f32 "
        "{%0,%1,%2,%3}, {%4,%5,%6,%7}, {%8,%9}, {%0,%1,%2,%3};"
        : "+f"(d[0]), "+f"(d[1]), "+f"(d[2]), "+f"(d[3])
        : "r"(a[0]), "r"(a[1]), "r"(a[2]), "r"(a[3]), "r"(b0), "r"(b1));
}

// ---------------- W conversion: W[k][n] fp32 -> Wt[n][k] bf16 hi/lo -------
__global__ __launch_bounds__(256) void conv_w(
    const float* __restrict__ Wq, const float* __restrict__ Wk,
    const float* __restrict__ Wv, const float* __restrict__ Wo)
{
    const float* W = (blockIdx.x == 0) ? Wq : (blockIdx.x == 1) ? Wk
                    : (blockIdx.x == 2) ? Wv : Wo;
    int t = threadIdx.x;
    int nr = t >> 1, half = t & 1;
#pragma unroll
    for (int j = 0; j < 8; j++) {
        int col8 = half * 8 + j;   // k-group (8 k's)
        int k0 = col8 * 8;
        float f[8];
#pragma unroll
        for (int i = 0; i < 8; i++) f[i] = W[(size_t)(k0 + i) * DIM + nr];
        uint4 hi, lo;
        pack8(f, hi, lo);
        g_bhi[blockIdx.x * 2048 + nr * 16 + col8] = hi;
        g_blo[blockIdx.x * 2048 + nr * 16 + col8] = lo;
    }
}

// ---------------- fused tensor-core GEMM ----------------------------------
// Loads/packs the A tile ONCE, then loops over nw weight matrices.
// split-bf16 via mma.sync: D = Ah*Bh + Ah*Bl + Al*Bh (fp32 accumulate)
// CTA: 128 rows x 128 cols, 512 threads, 16 warps in 4x4, warp tile 32x32
#define SM_BYTES (4 * 128 * ASTR * 2)

__global__ __launch_bounds__(512) void fused_gemm(
    const float* __restrict__ Xext,
    const float* __restrict__ b0, const float* __restrict__ b1,
    const float* __restrict__ b2, float* __restrict__ Yext,
    int wbase, int nw, int n, float s0, float s1, float s2)
{
    extern __shared__ __align__(16) char smem[];
    __nv_bfloat16* Ah = (__nv_bfloat16*)smem;            // [128][ASTR]
    __nv_bfloat16* Al = Ah + 128 * ASTR;
    __nv_bfloat16* Bh = Al + 128 * ASTR;                 // Wt rows = n, cols = k
    __nv_bfloat16* Bl = Bh + 128 * ASTR;
    const uint32_t HL_OFF = 128 * ASTR * 2;              // hi -> lo byte offset

    const float* X = (wbase == 3) ? g_agg : Xext;

    int tid = threadIdx.x;
    int row0 = blockIdx.x * 128;

    // ---- stage A (once): load fp32 X tile, split to bf16 hi/lo in SMEM ----
    {
        int r = tid >> 2, quarter = tid & 3;
        int grow = row0 + r;
#pragma unroll
        for (int j = 0; j < 4; j++) {
            int c0 = quarter * 32 + j * 8;
            float f[8] = {0, 0, 0, 0, 0, 0, 0, 0};
            if (grow < n) {
                float4 a = *(const float4*)&X[(size_t)grow * DIM + c0];
                float4 b = *(const float4*)&X[(size_t)grow * DIM + c0 + 4];
                f[0] = a.x; f[1] = a.y; f[2] = a.z; f[3] = a.w;
                f[4] = b.x; f[5] = b.y; f[6] = b.z; f[7] = b.w;
            }
            uint4 hi, lo;
            pack8(f, hi, lo);
            *(uint4*)&Ah[r * ASTR + c0] = hi;
            *(uint4*)&Al[r * ASTR + c0] = lo;
        }
    }
    __syncthreads();

    int wid = tid >> 5, lane = tid & 31;
    int wm = wid & 3, wn = wid >> 2;          // 4x4 warp grid, warp tile 32x32
    uint32_t aBase = smem_u32(Ah);
    uint32_t bBase = smem_u32(Bh);

    for (int m = 0; m < nw; m++) {
        int widx = wbase + m;
        const float* bias = (m == 0) ? b0 : (m == 1) ? b1 : b2;
        float scale = (m == 0) ? s0 : (m == 1) ? s1 : s2;
        float* Y = (wbase == 3) ? Yext
                 : (widx == 0) ? g_q : (widx == 1) ? g_k : g_v;

        // ---- load B for this weight set ----
        {
            const uint4* bh = g_bhi + widx * 2048;
            const uint4* bl = g_blo + widx * 2048;
#pragma unroll
            for (int i = 0; i < 4; i++) {
                int idx = tid * 4 + i;            // 0..2047
                int nrow = idx >> 4, c8 = idx & 15;
                *(uint4*)&Bh[nrow * ASTR + c8 * 8] = bh[idx];
                *(uint4*)&Bl[nrow * ASTR + c8 * 8] = bl[idx];
            }
        }
        __syncthreads();

        float acc[2][4][4];
#pragma unroll
        for (int mt = 0; mt < 2; mt++)
#pragma unroll
            for (int nt = 0; nt < 4; nt++)
#pragma unroll
                for (int i = 0; i < 4; i++) acc[mt][nt][i] = 0.0f;

#pragma unroll
        for (int ks = 0; ks < 8; ks++) {
            // A fragments: lane l -> &A[wm*32+mt*16 + l%16][ks*16 + (l/16)*8]
            uint32_t a_h[2][4], a_l[2][4];
#pragma unroll
            for (int mt = 0; mt < 2; mt++) {
                int arow = wm * 32 + mt * 16 + (lane & 15);
                int acol = ks * 16 + (lane >> 4) * 8;
                uint32_t ad = aBase + (uint32_t)(arow * ASTR + acol) * 2;
                ldm4(a_h[mt], ad);
                ldm4(a_l[mt], ad + HL_OFF);
            }
            // B fragments: x4 covers 2 ntiles each
            uint32_t b_h[2][4], b_l[2][4];
#pragma unroll
            for (int np = 0; np < 2; np++) {
                int brow = wn * 32 + np * 16 + (lane >> 4) * 8 + (lane & 7);
                int bcol = ks * 16 + ((lane >> 3) & 1) * 8;
                uint32_t bd = bBase + (uint32_t)(brow * ASTR + bcol) * 2;
                ldm4(b_h[np], bd);
                ldm4(b_l[np], bd + HL_OFF);
            }
#pragma unroll
            for (int mt = 0; mt < 2; mt++)
#pragma unroll
                for (int nt = 0; nt < 4; nt++) {
                    int np = nt >> 1, sel = (nt & 1) * 2;
                    mma16816(acc[mt][nt], a_h[mt], b_h[np][sel], b_h[np][sel + 1]);
                    mma16816(acc[mt][nt], a_h[mt], b_l[np][sel], b_l[np][sel + 1]);
                    mma16816(acc[mt][nt], a_l[mt], b_h[np][sel], b_h[np][sel + 1]);
                }
        }
        __syncthreads();   // all warps done reading B before next overwrite

        // ---- epilogue ----
#pragma unroll
        for (int mt = 0; mt < 2; mt++) {
            int rbase = row0 + wm * 32 + mt * 16 + (lane >> 2);
#pragma unroll
            for (int nt = 0; nt < 4; nt++) {
                int col = wn * 32 + nt * 8 + (lane & 3) * 2;
                float2 bv = *(const float2*)&bias[col];
                if (rbase < n) {
                    float2 o0;
                    o0.x = (acc[mt][nt][0] + bv.x) * scale;
                    o0.y = (acc[mt][nt][1] + bv.y) * scale;
                    *(float2*)&Y[(size_t)rbase * DIM + col] = o0;
                }
                if (rbase + 8 < n) {
                    float2 o1;
                    o1.x = (acc[mt][nt][2] + bv.x) * scale;
                    o1.y = (acc[mt][nt][3] + bv.y) * scale;
                    *(float2*)&Y[(size_t)(rbase + 8) * DIM + col] = o1;
                }
            }
        }
    }
}

// ---------------- counting sort of edges by dst ---------------------------
__global__ void zero_counts(int n) {
    int i = blockIdx.x * blockDim.x + threadIdx.x;
    int stride = gridDim.x * blockDim.x;
    for (int j = i; j < n; j += stride) { g_cnt[j] = 0; g_fill[j] = 0; }
}

__global__ void hist_kernel(const int* __restrict__ dst, int E) {
    int i = blockIdx.x * blockDim.x + threadIdx.x;
    int stride = gridDim.x * blockDim.x;
    for (int e = i; e < E; e += stride) atomicAdd(&g_cnt[dst[e]], 1);
}

__global__ __launch_bounds__(256) void scan_blocks(int n) {
    __shared__ int s[256];
    int t = threadIdx.x;
    int gi = blockIdx.x * 256 + t;
    int v = (gi < n) ? g_cnt[gi] : 0;
    s[t] = v;
    __syncthreads();
#pragma unroll
    for (int off = 1; off < 256; off <<= 1) {
        int tmp = (t >= off) ? s[t - off] : 0;
        __syncthreads();
        s[t] += tmp;
        __syncthreads();
    }
    if (gi < n) g_start[gi] = s[t] - v;
    if (t == 255) g_bsum[blockIdx.x] = s[255];
}

__global__ __launch_bounds__(NB_MAX) void scan_bsums(int nb) {
    __shared__ int s[NB_MAX];
    int t = threadIdx.x;
    int v = (t < nb) ? g_bsum[t] : 0;
    s[t] = v;
    __syncthreads();
#pragma unroll
    for (int off = 1; off < NB_MAX; off <<= 1) {
        int tmp = (t >= off) ? s[t - off] : 0;
        __syncthreads();
        s[t] += tmp;
        __syncthreads();
    }
    if (t < nb) g_boff[t] = s[t] - v;
}

__global__ void add_offsets(int n) {
    int i = blockIdx.x * blockDim.x + threadIdx.x;
    int stride = gridDim.x * blockDim.x;
    for (int j = i; j < n; j += stride) g_start[j] += g_boff[j >> 8];
}

__global__ void scatter_kernel(const int* __restrict__ src,
                               const int* __restrict__ dst, int E) {
    int i = blockIdx.x * blockDim.x + threadIdx.x;
    int stride = gridDim.x * blockDim.x;
    for (int e = i; e < E; e += stride) {
        int d = dst[e];
        int pos = g_start[d] + atomicAdd(&g_fill[d], 1);
        g_esrc[pos] = src[e];
    }
}

// ---------------- attention: warp per destination node --------------------
__global__ __launch_bounds__(256) void edge_sorted(int n) {
    int d = (int)((blockIdx.x * blockDim.x + threadIdx.x) >> 5);
    int lane = threadIdx.x & 31;
    if (d >= n) return;

    int base = g_start[d];
    int deg  = g_cnt[d];

    float4 kv = *(const float4*)&g_k[(size_t)d * DIM + lane * 4];
    float4 agg = make_float4(0.f, 0.f, 0.f, 0.f);
    float zacc = 0.0f;

    for (int chunk = 0; chunk < deg; chunk += 32) {
        int nmax = min(32, deg - chunk);
        int sv = (chunk + lane < deg) ? g_esrc[base + chunk + lane] : 0;
#pragma unroll 2
        for (int t = 0; t < nmax; t++) {
            int s = __shfl_sync(0xffffffffu, sv, t);
            float4 qv = *(const float4*)&g_q[(size_t)s * DIM + lane * 4];
            float p = qv.x * kv.x + qv.y * kv.y + qv.z * kv.z + qv.w * kv.w;
            p += __shfl_xor_sync(0xffffffffu, p, 1);
            p += __shfl_xor_sync(0xffffffffu, p, 2);
            float w = __expf(p);   // k pre-scaled; scores ~N(0,1), no overflow
            float4 vv = *(const float4*)&g_v[(size_t)s * DIM + lane * 4];
            agg.x += w * vv.x; agg.y += w * vv.y;
            agg.z += w * vv.z; agg.w += w * vv.w;
            zacc += w;
        }
    }

    float4 o = make_float4(0.f, 0.f, 0.f, 0.f);
    if (deg > 0) {
        float zinv = 1.0f / zacc;
        o.x = agg.x * zinv; o.y = agg.y * zinv;
        o.z = agg.z * zinv; o.w = agg.w * zinv;
    }
    *(float4*)&g_agg[(size_t)d * DIM + lane * 4] = o;
}

// ---------------- host entry ----------------------------------------------
extern "C" void kernel_launch(void* const* d_in, const int* in_sizes, int n_in,
                              void* d_out, int out_size)
{
    const float* x   = (const float*)d_in[0];
    const int*   src = (const int*)d_in[1];
    const int*   dst = (const int*)d_in[2];
    const float* Wq  = (const float*)d_in[3];
    const float* bq  = (const float*)d_in[4];
    const float* Wk  = (const float*)d_in[5];
    const float* bk  = (const float*)d_in[6];
    const float* Wv  = (const float*)d_in[7];
    const float* bv  = (const float*)d_in[8];
    const float* Wo  = (const float*)d_in[9];
    const float* bo  = (const float*)d_in[10];
    float* out = (float*)d_out;

    int n = in_sizes[0] / DIM;
    int E = in_sizes[1];
    int nb = (n + 255) / 256;
    int tiles = (n + 127) / 128;

    cudaFuncSetAttribute(fused_gemm, cudaFuncAttributeMaxDynamicSharedMemorySize, SM_BYTES);

    const float inv_sqrt_hd = 0.25f;  // 1/sqrt(16)

    // W conversion + fused q/k/v projection (A tile packed once)
    conv_w<<<4, 256>>>(Wq, Wk, Wv, Wo);
    fused_gemm<<<tiles, 512, SM_BYTES>>>(x, bq, bk, bv, nullptr, 0, 3, n,
                                         1.0f, inv_sqrt_hd, 1.0f);

    // counting sort of edges by dst
    zero_counts<<<256, 256>>>(n);
    hist_kernel<<<1024, 256>>>(dst, E);
    scan_blocks<<<nb, 256>>>(n);
    scan_bsums<<<1, NB_MAX>>>(nb);
    add_offsets<<<256, 256>>>(n);
    scatter_kernel<<<1024, 256>>>(src, dst, E);

    // fused attention (gather + softmax + aggregate, no atomics)
    edge_sorted<<<(n + 7) / 8, 256>>>(n);

    // output projection
    fused_gemm<<<tiles, 512, SM_BYTES>>>(nullptr, bo, bo, bo, out, 3, 1, n,
                                         1.0f, 1.0f, 1.0f);
}

// round 10
// speedup vs baseline: 2.0058x; 1.0579x over previous
#include <cuda_runtime.h>
#include <cuda_bf16.h>
#include <cuda_fp16.h>
#include <math.h>
#include <stdint.h>

#define DIM 128
#define H 8
#define NMAX 100000
#define EMAX 1600000
#define NB_MAX 512
#define ASTR 136                       // padded SMEM row stride (elements)

// ---------------- device scratch (no allocations allowed) ----------------
__device__ __half g_qh[(size_t)NMAX * DIM];   // q in fp16 (gather-heavy)
__device__ float  g_k[(size_t)NMAX * DIM];    // k fp32, pre-scaled by 1/sqrt(HD)
__device__ __half g_vh[(size_t)NMAX * DIM];   // v in fp16 (gather-heavy)
__device__ float  g_agg[(size_t)NMAX * DIM];  // NORMALIZED weighted sums
__device__ int    g_cnt[NMAX];
__device__ int    g_fill[NMAX];
__device__ int    g_start[NMAX];
__device__ int    g_bsum[NB_MAX];
__device__ int    g_boff[NB_MAX];
__device__ int    g_esrc[EMAX];
// W^T split into bf16 hi/lo, row-major [nout][k], 4 matrices
__device__ uint4 g_bhi[4 * 2048];
__device__ uint4 g_blo[4 * 2048];

// ---------------- helpers -------------------------------------------------
__device__ __forceinline__ uint32_t smem_u32(const void* p) {
    uint32_t a;
    asm("{ .reg .u64 t; cvta.to.shared.u64 t, %1; cvt.u32.u64 %0, t; }" : "=r"(a) : "l"(p));
    return a;
}

__device__ __forceinline__ void pack8(const float* f, uint4& hi, uint4& lo) {
    uint32_t hu[4], lu[4];
#pragma unroll
    for (int i = 0; i < 4; i++) {
        __nv_bfloat16 h0 = __float2bfloat16(f[2 * i]);
        __nv_bfloat16 h1 = __float2bfloat16(f[2 * i + 1]);
        float l0 = f[2 * i] - __bfloat162float(h0);      // exact (Sterbenz)
        float l1 = f[2 * i + 1] - __bfloat162float(h1);
        __nv_bfloat162 hp = __halves2bfloat162(h0, h1);
        __nv_bfloat162 lp = __halves2bfloat162(__float2bfloat16(l0), __float2bfloat16(l1));
        hu[i] = *(uint32_t*)&hp;
        lu[i] = *(uint32_t*)&lp;
    }
    hi = make_uint4(hu[0], hu[1], hu[2], hu[3]);
    lo = make_uint4(lu[0], lu[1], lu[2], lu[3]);
}

__device__ __forceinline__ void ldm4(uint32_t* r, uint32_t addr) {
    asm volatile("ldmatrix.sync.aligned.m8n8.x4.shared.b16 {%0,%1,%2,%3}, [%4];"
                 : "=r"(r[0]), "=r"(r[1]), "=r"(r[2]), "=r"(r[3]) : "r"(addr));
}

__device__ __forceinline__ void mma16816(float* d, const uint32_t* a, uint32_t b0, uint32_t b1) {
    asm volatile(
        "mma.sync.aligned.m16n8k16.row.col.f32.bf16.bf16.f32 "
        "{%0,%1,%2,%3}, {%4,%5,%6,%7}, {%8,%9}, {%0,%1,%2,%3};"
        : "+f"(d[0]), "+f"(d[1]), "+f"(d[2]), "+f"(d[3])
        : "r"(a[0]), "r"(a[1]), "r"(a[2]), "r"(a[3]), "r"(b0), "r"(b1));
}

// ---------------- W conversion: W[k][n] fp32 -> Wt[n][k] bf16 hi/lo -------
__global__ __launch_bounds__(256) void conv_w(
    const float* __restrict__ Wq, const float* __restrict__ Wk,
    const float* __restrict__ Wv, const float* __restrict__ Wo)
{
    const float* W = (blockIdx.x == 0) ? Wq : (blockIdx.x == 1) ? Wk
                    : (blockIdx.x == 2) ? Wv : Wo;
    int t = threadIdx.x;
    int nr = t >> 1, half = t & 1;
#pragma unroll
    for (int j = 0; j < 8; j++) {
        int col8 = half * 8 + j;   // k-group (8 k's)
        int k0 = col8 * 8;
        float f[8];
#pragma unroll
        for (int i = 0; i < 8; i++) f[i] = W[(size_t)(k0 + i) * DIM + nr];
        uint4 hi, lo;
        pack8(f, hi, lo);
        g_bhi[blockIdx.x * 2048 + nr * 16 + col8] = hi;
        g_blo[blockIdx.x * 2048 + nr * 16 + col8] = lo;
    }
}

// ---------------- fused tensor-core GEMM ----------------------------------
// Loads/packs the A tile ONCE, then loops over nw weight matrices.
// split-bf16 via mma.sync: D = Ah*Bh + Ah*Bl + Al*Bh (fp32 accumulate)
// CTA: 128 rows x 128 cols, 512 threads, 16 warps in 4x4, warp tile 32x32
// Output: widx 0 -> g_qh (fp16), widx 1 -> g_k (fp32), widx 2 -> g_vh (fp16),
//         wbase 3 -> Yext (fp32)
#define SM_BYTES (4 * 128 * ASTR * 2)

__global__ __launch_bounds__(512) void fused_gemm(
    const float* __restrict__ Xext,
    const float* __restrict__ b0, const float* __restrict__ b1,
    const float* __restrict__ b2, float* __restrict__ Yext,
    int wbase, int nw, int n, float s0, float s1, float s2)
{
    extern __shared__ __align__(16) char smem[];
    __nv_bfloat16* Ah = (__nv_bfloat16*)smem;            // [128][ASTR]
    __nv_bfloat16* Al = Ah + 128 * ASTR;
    __nv_bfloat16* Bh = Al + 128 * ASTR;                 // Wt rows = n, cols = k
    __nv_bfloat16* Bl = Bh + 128 * ASTR;
    const uint32_t HL_OFF = 128 * ASTR * 2;              // hi -> lo byte offset

    const float* X = (wbase == 3) ? g_agg : Xext;

    int tid = threadIdx.x;
    int row0 = blockIdx.x * 128;

    // ---- stage A (once): load fp32 X tile, split to bf16 hi/lo in SMEM ----
    {
        int r = tid >> 2, quarter = tid & 3;
        int grow = row0 + r;
#pragma unroll
        for (int j = 0; j < 4; j++) {
            int c0 = quarter * 32 + j * 8;
            float f[8] = {0, 0, 0, 0, 0, 0, 0, 0};
            if (grow < n) {
                float4 a = *(const float4*)&X[(size_t)grow * DIM + c0];
                float4 b = *(const float4*)&X[(size_t)grow * DIM + c0 + 4];
                f[0] = a.x; f[1] = a.y; f[2] = a.z; f[3] = a.w;
                f[4] = b.x; f[5] = b.y; f[6] = b.z; f[7] = b.w;
            }
            uint4 hi, lo;
            pack8(f, hi, lo);
            *(uint4*)&Ah[r * ASTR + c0] = hi;
            *(uint4*)&Al[r * ASTR + c0] = lo;
        }
    }
    __syncthreads();

    int wid = tid >> 5, lane = tid & 31;
    int wm = wid & 3, wn = wid >> 2;          // 4x4 warp grid, warp tile 32x32
    uint32_t aBase = smem_u32(Ah);
    uint32_t bBase = smem_u32(Bh);

    for (int m = 0; m < nw; m++) {
        int widx = wbase + m;
        const float* bias = (m == 0) ? b0 : (m == 1) ? b1 : b2;
        float scale = (m == 0) ? s0 : (m == 1) ? s1 : s2;
        int toHalf = (wbase == 0) && (widx != 1);
        float* Yf = (wbase == 3) ? Yext : g_k;
        __half* Yh = (widx == 0) ? g_qh : g_vh;

        // ---- load B for this weight set ----
        {
            const uint4* bh = g_bhi + widx * 2048;
            const uint4* bl = g_blo + widx * 2048;
#pragma unroll
            for (int i = 0; i < 4; i++) {
                int idx = tid * 4 + i;            // 0..2047
                int nrow = idx >> 4, c8 = idx & 15;
                *(uint4*)&Bh[nrow * ASTR + c8 * 8] = bh[idx];
                *(uint4*)&Bl[nrow * ASTR + c8 * 8] = bl[idx];
            }
        }
        __syncthreads();

        float acc[2][4][4];
#pragma unroll
        for (int mt = 0; mt < 2; mt++)
#pragma unroll
            for (int nt = 0; nt < 4; nt++)
#pragma unroll
                for (int i = 0; i < 4; i++) acc[mt][nt][i] = 0.0f;

#pragma unroll
        for (int ks = 0; ks < 8; ks++) {
            uint32_t a_h[2][4], a_l[2][4];
#pragma unroll
            for (int mt = 0; mt < 2; mt++) {
                int arow = wm * 32 + mt * 16 + (lane & 15);
                int acol = ks * 16 + (lane >> 4) * 8;
                uint32_t ad = aBase + (uint32_t)(arow * ASTR + acol) * 2;
                ldm4(a_h[mt], ad);
                ldm4(a_l[mt], ad + HL_OFF);
            }
            uint32_t b_h[2][4], b_l[2][4];
#pragma unroll
            for (int np = 0; np < 2; np++) {
                int brow = wn * 32 + np * 16 + (lane >> 4) * 8 + (lane & 7);
                int bcol = ks * 16 + ((lane >> 3) & 1) * 8;
                uint32_t bd = bBase + (uint32_t)(brow * ASTR + bcol) * 2;
                ldm4(b_h[np], bd);
                ldm4(b_l[np], bd + HL_OFF);
            }
#pragma unroll
            for (int mt = 0; mt < 2; mt++)
#pragma unroll
                for (int nt = 0; nt < 4; nt++) {
                    int np = nt >> 1, sel = (nt & 1) * 2;
                    mma16816(acc[mt][nt], a_h[mt], b_h[np][sel], b_h[np][sel + 1]);
                    mma16816(acc[mt][nt], a_h[mt], b_l[np][sel], b_l[np][sel + 1]);
                    mma16816(acc[mt][nt], a_l[mt], b_h[np][sel], b_h[np][sel + 1]);
                }
        }
        __syncthreads();   // all warps done reading B before next overwrite

        // ---- epilogue ----
#pragma unroll
        for (int mt = 0; mt < 2; mt++) {
            int rbase = row0 + wm * 32 + mt * 16 + (lane >> 2);
#pragma unroll
            for (int nt = 0; nt < 4; nt++) {
                int col = wn * 32 + nt * 8 + (lane & 3) * 2;
                float2 bv = *(const float2*)&bias[col];
                float x0 = (acc[mt][nt][0] + bv.x) * scale;
                float y0 = (acc[mt][nt][1] + bv.y) * scale;
                float x1 = (acc[mt][nt][2] + bv.x) * scale;
                float y1 = (acc[mt][nt][3] + bv.y) * scale;
                if (toHalf) {
                    if (rbase < n)
                        *(__half2*)&Yh[(size_t)rbase * DIM + col] = __floats2half2_rn(x0, y0);
                    if (rbase + 8 < n)
                        *(__half2*)&Yh[(size_t)(rbase + 8) * DIM + col] = __floats2half2_rn(x1, y1);
                } else {
                    if (rbase < n)
                        *(float2*)&Yf[(size_t)rbase * DIM + col] = make_float2(x0, y0);
                    if (rbase + 8 < n)
                        *(float2*)&Yf[(size_t)(rbase + 8) * DIM + col] = make_float2(x1, y1);
                }
            }
        }
    }
}

// ---------------- counting sort of edges by dst ---------------------------
__global__ void zero_counts(int n) {
    int i = blockIdx.x * blockDim.x + threadIdx.x;
    int stride = gridDim.x * blockDim.x;
    for (int j = i; j < n; j += stride) { g_cnt[j] = 0; g_fill[j] = 0; }
}

__global__ void hist_kernel(const int* __restrict__ dst, int E) {
    int i = blockIdx.x * blockDim.x + threadIdx.x;
    int stride = gridDim.x * blockDim.x;
    for (int e = i; e < E; e += stride) atomicAdd(&g_cnt[dst[e]], 1);
}

__global__ __launch_bounds__(256) void scan_blocks(int n) {
    __shared__ int s[256];
    int t = threadIdx.x;
    int gi = blockIdx.x * 256 + t;
    int v = (gi < n) ? g_cnt[gi] : 0;
    s[t] = v;
    __syncthreads();
#pragma unroll
    for (int off = 1; off < 256; off <<= 1) {
        int tmp = (t >= off) ? s[t - off] : 0;
        __syncthreads();
        s[t] += tmp;
        __syncthreads();
    }
    if (gi < n) g_start[gi] = s[t] - v;
    if (t == 255) g_bsum[blockIdx.x] = s[255];
}

__global__ __launch_bounds__(NB_MAX) void scan_bsums(int nb) {
    __shared__ int s[NB_MAX];
    int t = threadIdx.x;
    int v = (t < nb) ? g_bsum[t] : 0;
    s[t] = v;
    __syncthreads();
#pragma unroll
    for (int off = 1; off < NB_MAX; off <<= 1) {
        int tmp = (t >= off) ? s[t - off] : 0;
        __syncthreads();
        s[t] += tmp;
        __syncthreads();
    }
    if (t < nb) g_boff[t] = s[t] - v;
}

__global__ void add_offsets(int n) {
    int i = blockIdx.x * blockDim.x + threadIdx.x;
    int stride = gridDim.x * blockDim.x;
    for (int j = i; j < n; j += stride) g_start[j] += g_boff[j >> 8];
}

__global__ void scatter_kernel(const int* __restrict__ src,
                               const int* __restrict__ dst, int E) {
    int i = blockIdx.x * blockDim.x + threadIdx.x;
    int stride = gridDim.x * blockDim.x;
    for (int e = i; e < E; e += stride) {
        int d = dst[e];
        int pos = g_start[d] + atomicAdd(&g_fill[d], 1);
        g_esrc[pos] = src[e];
    }
}

// ---------------- attention: warp per destination node --------------------
// q/v gathered in fp16 (halves L2 traffic), k + accumulators fp32
__global__ __launch_bounds__(256) void edge_sorted(int n) {
    int d = (int)((blockIdx.x * blockDim.x + threadIdx.x) >> 5);
    int lane = threadIdx.x & 31;
    if (d >= n) return;

    int base = g_start[d];
    int deg  = g_cnt[d];

    float4 kv = *(const float4*)&g_k[(size_t)d * DIM + lane * 4];
    float4 agg = make_float4(0.f, 0.f, 0.f, 0.f);
    float zacc = 0.0f;

    for (int chunk = 0; chunk < deg; chunk += 32) {
        int nmax = min(32, deg - chunk);
        int sv = (chunk + lane < deg) ? g_esrc[base + chunk + lane] : 0;
#pragma unroll 2
        for (int t = 0; t < nmax; t++) {
            int s = __shfl_sync(0xffffffffu, sv, t);
            uint2 qu = *(const uint2*)&g_qh[(size_t)s * DIM + lane * 4];
            float2 q01 = __half22float2(*(__half2*)&qu.x);
            float2 q23 = __half22float2(*(__half2*)&qu.y);
            float p = q01.x * kv.x + q01.y * kv.y + q23.x * kv.z + q23.y * kv.w;
            p += __shfl_xor_sync(0xffffffffu, p, 1);
            p += __shfl_xor_sync(0xffffffffu, p, 2);
            float w = __expf(p);   // k pre-scaled; scores ~N(0,1), no overflow
            uint2 vu = *(const uint2*)&g_vh[(size_t)s * DIM + lane * 4];
            float2 v01 = __half22float2(*(__half2*)&vu.x);
            float2 v23 = __half22float2(*(__half2*)&vu.y);
            agg.x += w * v01.x; agg.y += w * v01.y;
            agg.z += w * v23.x; agg.w += w * v23.y;
            zacc += w;
        }
    }

    float4 o = make_float4(0.f, 0.f, 0.f, 0.f);
    if (deg > 0) {
        float zinv = 1.0f / zacc;
        o.x = agg.x * zinv; o.y = agg.y * zinv;
        o.z = agg.z * zinv; o.w = agg.w * zinv;
    }
    *(float4*)&g_agg[(size_t)d * DIM + lane * 4] = o;
}

// ---------------- host entry ----------------------------------------------
extern "C" void kernel_launch(void* const* d_in, const int* in_sizes, int n_in,
                              void* d_out, int out_size)
{
    const float* x   = (const float*)d_in[0];
    const int*   src = (const int*)d_in[1];
    const int*   dst = (const int*)d_in[2];
    const float* Wq  = (const float*)d_in[3];
    const float* bq  = (const float*)d_in[4];
    const float* Wk  = (const float*)d_in[5];
    const float* bk  = (const float*)d_in[6];
    const float* Wv  = (const float*)d_in[7];
    const float* bv  = (const float*)d_in[8];
    const float* Wo  = (const float*)d_in[9];
    const float* bo  = (const float*)d_in[10];
    float* out = (float*)d_out;

    int n = in_sizes[0] / DIM;
    int E = in_sizes[1];
    int nb = (n + 255) / 256;
    int tiles = (n + 127) / 128;

    cudaFuncSetAttribute(fused_gemm, cudaFuncAttributeMaxDynamicSharedMemorySize, SM_BYTES);

    const float inv_sqrt_hd = 0.25f;  // 1/sqrt(16)

    // W conversion + fused q/k/v projection (A tile packed once)
    conv_w<<<4, 256>>>(Wq, Wk, Wv, Wo);
    fused_gemm<<<tiles, 512, SM_BYTES>>>(x, bq, bk, bv, nullptr, 0, 3, n,
                                         1.0f, inv_sqrt_hd, 1.0f);

    // counting sort of edges by dst
    zero_counts<<<256, 256>>>(n);
    hist_kernel<<<1024, 256>>>(dst, E);
    scan_blocks<<<nb, 256>>>(n);
    scan_bsums<<<1, NB_MAX>>>(nb);
    add_offsets<<<256, 256>>>(n);
    scatter_kernel<<<1024, 256>>>(src, dst, E);

    // fused attention (gather + softmax + aggregate, no atomics)
    edge_sorted<<<(n + 7) / 8, 256>>>(n);

    // output projection
    fused_gemm<<<tiles, 512, SM_BYTES>>>(nullptr, bo, bo, bo, out, 3, 1, n,
                                         1.0f, 1.0f, 1.0f);
}

// round 12
// speedup vs baseline: 2.1149x; 1.0544x over previous
#include <cuda_runtime.h>
#include <cuda_bf16.h>
#include <cuda_fp16.h>
#include <math.h>
#include <stdint.h>

#define DIM 128
#define H 8
#define NMAX 100000
#define EMAX 1600000
#define NB_MAX 512
#define ASTR 136                       // padded SMEM row stride (elements)

// ---------------- device scratch (no allocations allowed) ----------------
__device__ __half g_qh[(size_t)NMAX * DIM];   // q in fp16 (gather-heavy)
__device__ float  g_k[(size_t)NMAX * DIM];    // k fp32, pre-scaled by 1/sqrt(HD)
__device__ __half g_vh[(size_t)NMAX * DIM];   // v in fp16 (gather-heavy)
__device__ float  g_agg[(size_t)NMAX * DIM];  // NORMALIZED weighted sums
__device__ int    g_cnt[NMAX];
__device__ int    g_fill[NMAX];
__device__ int    g_start[NMAX];
__device__ int    g_bsum[NB_MAX];
__device__ int    g_boff[NB_MAX];
__device__ int    g_esrc[EMAX];
// W^T split into bf16 hi/lo, row-major [nout][k], 4 matrices
__device__ uint4 g_bhi[4 * 2048];
__device__ uint4 g_blo[4 * 2048];

// ---------------- helpers -------------------------------------------------
__device__ __forceinline__ uint32_t smem_u32(const void* p) {
    uint32_t a;
    asm("{ .reg .u64 t; cvta.to.shared.u64 t, %1; cvt.u32.u64 %0, t; }" : "=r"(a) : "l"(p));
    return a;
}

__device__ __forceinline__ void pack8(const float* f, uint4& hi, uint4& lo) {
    uint32_t hu[4], lu[4];
#pragma unroll
    for (int i = 0; i < 4; i++) {
        __nv_bfloat16 h0 = __float2bfloat16(f[2 * i]);
        __nv_bfloat16 h1 = __float2bfloat16(f[2 * i + 1]);
        float l0 = f[2 * i] - __bfloat162float(h0);      // exact (Sterbenz)
        float l1 = f[2 * i + 1] - __bfloat162float(h1);
        __nv_bfloat162 hp = __halves2bfloat162(h0, h1);
        __nv_bfloat162 lp = __halves2bfloat162(__float2bfloat16(l0), __float2bfloat16(l1));
        hu[i] = *(uint32_t*)&hp;
        lu[i] = *(uint32_t*)&lp;
    }
    hi = make_uint4(hu[0], hu[1], hu[2], hu[3]);
    lo = make_uint4(lu[0], lu[1], lu[2], lu[3]);
}

__device__ __forceinline__ void ldm4(uint32_t* r, uint32_t addr) {
    asm volatile("ldmatrix.sync.aligned.m8n8.x4.shared.b16 {%0,%1,%2,%3}, [%4];"
                 : "=r"(r[0]), "=r"(r[1]), "=r"(r[2]), "=r"(r[3]) : "r"(addr));
}

__device__ __forceinline__ void mma16816(float* d, const uint32_t* a, uint32_t b0, uint32_t b1) {
    asm volatile(
        "mma.sync.aligned.m16n8k16.row.col.f32.bf16.bf16.f32 "
        "{%0,%1,%2,%3}, {%4,%5,%6,%7}, {%8,%9}, {%0,%1,%2,%3};"
        : "+f"(d[0]), "+f"(d[1]), "+f"(d[2]), "+f"(d[3])
        : "r"(a[0]), "r"(a[1]), "r"(a[2]), "r"(a[3]), "r"(b0), "r"(b1));
}

// ---------------- W conversion: W[k][n] fp32 -> Wt[n][k] bf16 hi/lo -------
__global__ __launch_bounds__(256) void conv_w(
    const float* __restrict__ Wq, const float* __restrict__ Wk,
    const float* __restrict__ Wv, const float* __restrict__ Wo)
{
    const float* W = (blockIdx.x == 0) ? Wq : (blockIdx.x == 1) ? Wk
                    : (blockIdx.x == 2) ? Wv : Wo;
    int t = threadIdx.x;
    int nr = t >> 1, half = t & 1;
#pragma unroll
    for (int j = 0; j < 8; j++) {
        int col8 = half * 8 + j;   // k-group (8 k's)
        int k0 = col8 * 8;
        float f[8];
#pragma unroll
        for (int i = 0; i < 8; i++) f[i] = W[(size_t)(k0 + i) * DIM + nr];
        uint4 hi, lo;
        pack8(f, hi, lo);
        g_bhi[blockIdx.x * 2048 + nr * 16 + col8] = hi;
        g_blo[blockIdx.x * 2048 + nr * 16 + col8] = lo;
    }
}

// ---------------- fused tensor-core GEMM ----------------------------------
// Loads/packs the A tile ONCE, then loops over nw weight matrices.
// split-bf16 via mma.sync: D = Ah*Bh + Ah*Bl + Al*Bh (fp32 accumulate)
// CTA: 128 rows x 128 cols, 512 threads, 16 warps in 4x4, warp tile 32x32
// Output: widx 0 -> g_qh (fp16), widx 1 -> g_k (fp32), widx 2 -> g_vh (fp16),
//         wbase 3 -> Yext (fp32)
#define SM_BYTES (4 * 128 * ASTR * 2)

__global__ __launch_bounds__(512) void fused_gemm(
    const float* __restrict__ Xext,
    const float* __restrict__ b0, const float* __restrict__ b1,
    const float* __restrict__ b2, float* __restrict__ Yext,
    int wbase, int nw, int n, float s0, float s1, float s2)
{
    extern __shared__ __align__(16) char smem[];
    __nv_bfloat16* Ah = (__nv_bfloat16*)smem;            // [128][ASTR]
    __nv_bfloat16* Al = Ah + 128 * ASTR;
    __nv_bfloat16* Bh = Al + 128 * ASTR;                 // Wt rows = n, cols = k
    __nv_bfloat16* Bl = Bh + 128 * ASTR;
    const uint32_t HL_OFF = 128 * ASTR * 2;              // hi -> lo byte offset

    const float* X = (wbase == 3) ? g_agg : Xext;

    int tid = threadIdx.x;
    int row0 = blockIdx.x * 128;

    // ---- stage A (once): load fp32 X tile, split to bf16 hi/lo in SMEM ----
    {
        int r = tid >> 2, quarter = tid & 3;
        int grow = row0 + r;
#pragma unroll
        for (int j = 0; j < 4; j++) {
            int c0 = quarter * 32 + j * 8;
            float f[8] = {0, 0, 0, 0, 0, 0, 0, 0};
            if (grow < n) {
                float4 a = *(const float4*)&X[(size_t)grow * DIM + c0];
                float4 b = *(const float4*)&X[(size_t)grow * DIM + c0 + 4];
                f[0] = a.x; f[1] = a.y; f[2] = a.z; f[3] = a.w;
                f[4] = b.x; f[5] = b.y; f[6] = b.z; f[7] = b.w;
            }
            uint4 hi, lo;
            pack8(f, hi, lo);
            *(uint4*)&Ah[r * ASTR + c0] = hi;
            *(uint4*)&Al[r * ASTR + c0] = lo;
        }
    }
    __syncthreads();

    int wid = tid >> 5, lane = tid & 31;
    int wm = wid & 3, wn = wid >> 2;          // 4x4 warp grid, warp tile 32x32
    uint32_t aBase = smem_u32(Ah);
    uint32_t bBase = smem_u32(Bh);

    for (int m = 0; m < nw; m++) {
        int widx = wbase + m;
        const float* bias = (m == 0) ? b0 : (m == 1) ? b1 : b2;
        float scale = (m == 0) ? s0 : (m == 1) ? s1 : s2;
        int toHalf = (wbase == 0) && (widx != 1);
        float* Yf = (wbase == 3) ? Yext : g_k;
        __half* Yh = (widx == 0) ? g_qh : g_vh;

        // ---- load B for this weight set ----
        {
            const uint4* bh = g_bhi + widx * 2048;
            const uint4* bl = g_blo + widx * 2048;
#pragma unroll
            for (int i = 0; i < 4; i++) {
                int idx = tid * 4 + i;            // 0..2047
                int nrow = idx >> 4, c8 = idx & 15;
                *(uint4*)&Bh[nrow * ASTR + c8 * 8] = bh[idx];
                *(uint4*)&Bl[nrow * ASTR + c8 * 8] = bl[idx];
            }
        }
        __syncthreads();

        float acc[2][4][4];
#pragma unroll
        for (int mt = 0; mt < 2; mt++)
#pragma unroll
            for (int nt = 0; nt < 4; nt++)
#pragma unroll
                for (int i = 0; i < 4; i++) acc[mt][nt][i] = 0.0f;

#pragma unroll
        for (int ks = 0; ks < 8; ks++) {
            uint32_t a_h[2][4], a_l[2][4];
#pragma unroll
            for (int mt = 0; mt < 2; mt++) {
                int arow = wm * 32 + mt * 16 + (lane & 15);
                int acol = ks * 16 + (lane >> 4) * 8;
                uint32_t ad = aBase + (uint32_t)(arow * ASTR + acol) * 2;
                ldm4(a_h[mt], ad);
                ldm4(a_l[mt], ad + HL_OFF);
            }
            uint32_t b_h[2][4], b_l[2][4];
#pragma unroll
            for (int np = 0; np < 2; np++) {
                int brow = wn * 32 + np * 16 + (lane >> 4) * 8 + (lane & 7);
                int bcol = ks * 16 + ((lane >> 3) & 1) * 8;
                uint32_t bd = bBase + (uint32_t)(brow * ASTR + bcol) * 2;
                ldm4(b_h[np], bd);
                ldm4(b_l[np], bd + HL_OFF);
            }
#pragma unroll
            for (int mt = 0; mt < 2; mt++)
#pragma unroll
                for (int nt = 0; nt < 4; nt++) {
                    int np = nt >> 1, sel = (nt & 1) * 2;
                    mma16816(acc[mt][nt], a_h[mt], b_h[np][sel], b_h[np][sel + 1]);
                    mma16816(acc[mt][nt], a_h[mt], b_l[np][sel], b_l[np][sel + 1]);
                    mma16816(acc[mt][nt], a_l[mt], b_h[np][sel], b_h[np][sel + 1]);
                }
        }
        __syncthreads();   // all warps done reading B before next overwrite

        // ---- epilogue ----
#pragma unroll
        for (int mt = 0; mt < 2; mt++) {
            int rbase = row0 + wm * 32 + mt * 16 + (lane >> 2);
#pragma unroll
            for (int nt = 0; nt < 4; nt++) {
                int col = wn * 32 + nt * 8 + (lane & 3) * 2;
                float2 bv = *(const float2*)&bias[col];
                float x0 = (acc[mt][nt][0] + bv.x) * scale;
                float y0 = (acc[mt][nt][1] + bv.y) * scale;
                float x1 = (acc[mt][nt][2] + bv.x) * scale;
                float y1 = (acc[mt][nt][3] + bv.y) * scale;
                if (toHalf) {
                    if (rbase < n)
                        *(__half2*)&Yh[(size_t)rbase * DIM + col] = __floats2half2_rn(x0, y0);
                    if (rbase + 8 < n)
                        *(__half2*)&Yh[(size_t)(rbase + 8) * DIM + col] = __floats2half2_rn(x1, y1);
                } else {
                    if (rbase < n)
                        *(float2*)&Yf[(size_t)rbase * DIM + col] = make_float2(x0, y0);
                    if (rbase + 8 < n)
                        *(float2*)&Yf[(size_t)(rbase + 8) * DIM + col] = make_float2(x1, y1);
                }
            }
        }
    }
}

// ---------------- counting sort of edges by dst ---------------------------
__global__ void zero_counts(int n) {
    int i = blockIdx.x * blockDim.x + threadIdx.x;
    int stride = gridDim.x * blockDim.x;
    for (int j = i; j < n; j += stride) { g_cnt[j] = 0; g_fill[j] = 0; }
}

__global__ void hist_kernel(const int* __restrict__ dst, int E) {
    int i = blockIdx.x * blockDim.x + threadIdx.x;
    int stride = gridDim.x * blockDim.x;
    for (int e = i; e < E; e += stride) atomicAdd(&g_cnt[dst[e]], 1);
}

__global__ __launch_bounds__(256) void scan_blocks(int n) {
    __shared__ int s[256];
    int t = threadIdx.x;
    int gi = blockIdx.x * 256 + t;
    int v = (gi < n) ? g_cnt[gi] : 0;
    s[t] = v;
    __syncthreads();
#pragma unroll
    for (int off = 1; off < 256; off <<= 1) {
        int tmp = (t >= off) ? s[t - off] : 0;
        __syncthreads();
        s[t] += tmp;
        __syncthreads();
    }
    if (gi < n) g_start[gi] = s[t] - v;
    if (t == 255) g_bsum[blockIdx.x] = s[255];
}

__global__ __launch_bounds__(NB_MAX) void scan_bsums(int nb) {
    __shared__ int s[NB_MAX];
    int t = threadIdx.x;
    int v = (t < nb) ? g_bsum[t] : 0;
    s[t] = v;
    __syncthreads();
#pragma unroll
    for (int off = 1; off < NB_MAX; off <<= 1) {
        int tmp = (t >= off) ? s[t - off] : 0;
        __syncthreads();
        s[t] += tmp;
        __syncthreads();
    }
    if (t < nb) g_boff[t] = s[t] - v;
}

__global__ void add_offsets(int n) {
    int i = blockIdx.x * blockDim.x + threadIdx.x;
    int stride = gridDim.x * blockDim.x;
    for (int j = i; j < n; j += stride) g_start[j] += g_boff[j >> 8];
}

__global__ void scatter_kernel(const int* __restrict__ src,
                               const int* __restrict__ dst, int E) {
    int i = blockIdx.x * blockDim.x + threadIdx.x;
    int stride = gridDim.x * blockDim.x;
    for (int e = i; e < E; e += stride) {
        int d = dst[e];
        int pos = g_start[d] + atomicAdd(&g_fill[d], 1);
        g_esrc[pos] = src[e];
    }
}

// ---------------- attention: warp per destination node --------------------
// q/v gathered in fp16 (halves L2 traffic), k + accumulators fp32
__global__ __launch_bounds__(256) void edge_sorted(int n) {
    int d = (int)((blockIdx.x * blockDim.x + threadIdx.x) >> 5);
    int lane = threadIdx.x & 31;
    if (d >= n) return;

    int base = g_start[d];
    int deg  = g_cnt[d];

    float4 kv = *(const float4*)&g_k[(size_t)d * DIM + lane * 4];
    float4 agg = make_float4(0.f, 0.f, 0.f, 0.f);
    float zacc = 0.0f;

    for (int chunk = 0; chunk < deg; chunk += 32) {
        int nmax = min(32, deg - chunk);
        int sv = (chunk + lane < deg) ? g_esrc[base + chunk + lane] : 0;
#pragma unroll 2
        for (int t = 0; t < nmax; t++) {
            int s = __shfl_sync(0xffffffffu, sv, t);
            uint2 qu = *(const uint2*)&g_qh[(size_t)s * DIM + lane * 4];
            float2 q01 = __half22float2(*(__half2*)&qu.x);
            float2 q23 = __half22float2(*(__half2*)&qu.y);
            float p = q01.x * kv.x + q01.y * kv.y + q23.x * kv.z + q23.y * kv.w;
            p += __shfl_xor_sync(0xffffffffu, p, 1);
            p += __shfl_xor_sync(0xffffffffu, p, 2);
            float w = __expf(p);   // k pre-scaled; scores ~N(0,1), no overflow
            uint2 vu = *(const uint2*)&g_vh[(size_t)s * DIM + lane * 4];
            float2 v01 = __half22float2(*(__half2*)&vu.x);
            float2 v23 = __half22float2(*(__half2*)&vu.y);
            agg.x += w * v01.x; agg.y += w * v01.y;
            agg.z += w * v23.x; agg.w += w * v23.y;
            zacc += w;
        }
    }

    float4 o = make_float4(0.f, 0.f, 0.f, 0.f);
    if (deg > 0) {
        float zinv = 1.0f / zacc;
        o.x = agg.x * zinv; o.y = agg.y * zinv;
        o.z = agg.z * zinv; o.w = agg.w * zinv;
    }
    *(float4*)&g_agg[(size_t)d * DIM + lane * 4] = o;
}

// ---------------- host entry ----------------------------------------------
extern "C" void kernel_launch(void* const* d_in, const int* in_sizes, int n_in,
                              void* d_out, int out_size)
{
    const float* x   = (const float*)d_in[0];
    const int*   src = (const int*)d_in[1];
    const int*   dst = (const int*)d_in[2];
    const float* Wq  = (const float*)d_in[3];
    const float* bq  = (const float*)d_in[4];
    const float* Wk  = (const float*)d_in[5];
    const float* bk  = (const float*)d_in[6];
    const float* Wv  = (const float*)d_in[7];
    const float* bv  = (const float*)d_in[8];
    const float* Wo  = (const float*)d_in[9];
    const float* bo  = (const float*)d_in[10];
    float* out = (float*)d_out;

    int n = in_sizes[0] / DIM;
    int E = in_sizes[1];
    int nb = (n + 255) / 256;
    int tiles = (n + 127) / 128;

    cudaFuncSetAttribute(fused_gemm, cudaFuncAttributeMaxDynamicSharedMemorySize, SM_BYTES);

    const float inv_sqrt_hd = 0.25f;  // 1/sqrt(16)

    // Fork a side stream for the edge sort (independent of the GEMMs).
    // Host-side stream/event creation happens only during capture (graph
    // replays re-execute only the captured device work); no device memory
    // is allocated.
    cudaStream_t s2;
    cudaStreamCreateWithFlags(&s2, cudaStreamNonBlocking);
    cudaEvent_t eFork, eJoin;
    cudaEventCreateWithFlags(&eFork, cudaEventDisableTiming);
    cudaEventCreateWithFlags(&eJoin, cudaEventDisableTiming);

    cudaEventRecord(eFork, 0);
    cudaStreamWaitEvent(s2, eFork, 0);

    // ---- side stream: counting sort of edges by dst (~60us, hidden) ----
    zero_counts<<<256, 256, 0, s2>>>(n);
    hist_kernel<<<1024, 256, 0, s2>>>(dst, E);
    scan_blocks<<<nb, 256, 0, s2>>>(n);
    scan_bsums<<<1, NB_MAX, 0, s2>>>(nb);
    add_offsets<<<256, 256, 0, s2>>>(n);
    scatter_kernel<<<1024, 256, 0, s2>>>(src, dst, E);
    cudaEventRecord(eJoin, s2);

    // ---- main stream: W conversion + fused q/k/v projection ----
    conv_w<<<4, 256>>>(Wq, Wk, Wv, Wo);
    fused_gemm<<<tiles, 512, SM_BYTES>>>(x, bq, bk, bv, nullptr, 0, 3, n,
                                         1.0f, inv_sqrt_hd, 1.0f);

    // join: attention needs both the sorted edges and q/k/v
    cudaStreamWaitEvent(0, eJoin, 0);
    edge_sorted<<<(n + 7) / 8, 256>>>(n);

    // output projection
    fused_gemm<<<tiles, 512, SM_BYTES>>>(nullptr, bo, bo, bo, out, 3, 1, n,
                                         1.0f, 1.0f, 1.0f);
}

// round 13
// speedup vs baseline: 2.3768x; 1.1238x over previous
#include <cuda_runtime.h>
#include <cuda_bf16.h>
#include <cuda_fp16.h>
#include <math.h>
#include <stdint.h>

#define DIM 128
#define H 8
#define NMAX 100000
#define EMAX 1600000
#define NB_MAX 512
#define ASTR 136                       // padded SMEM row stride (elements)

// ---------------- device scratch (no allocations allowed) ----------------
// q and v interleaved per node: 32 lanes x 16B = [q0q1q2q3 v0v1v2v3] halves
__device__ uint4  g_qv[(size_t)NMAX * 32];
__device__ float  g_k[(size_t)NMAX * DIM];    // k fp32, pre-scaled by 1/sqrt(HD)
__device__ float  g_agg[(size_t)NMAX * DIM];  // NORMALIZED weighted sums
__device__ int    g_cnt[NMAX];
__device__ int    g_fill[NMAX];
__device__ int    g_start[NMAX];
__device__ int    g_bsum[NB_MAX];
__device__ int    g_boff[NB_MAX];
__device__ int    g_esrc[EMAX];
// W^T split into bf16 hi/lo, row-major [nout][k], 4 matrices
__device__ uint4 g_bhi[4 * 2048];
__device__ uint4 g_blo[4 * 2048];

// ---------------- helpers -------------------------------------------------
__device__ __forceinline__ uint32_t smem_u32(const void* p) {
    uint32_t a;
    asm("{ .reg .u64 t; cvta.to.shared.u64 t, %1; cvt.u32.u64 %0, t; }" : "=r"(a) : "l"(p));
    return a;
}

__device__ __forceinline__ void pack8(const float* f, uint4& hi, uint4& lo) {
    uint32_t hu[4], lu[4];
#pragma unroll
    for (int i = 0; i < 4; i++) {
        __nv_bfloat16 h0 = __float2bfloat16(f[2 * i]);
        __nv_bfloat16 h1 = __float2bfloat16(f[2 * i + 1]);
        float l0 = f[2 * i] - __bfloat162float(h0);      // exact (Sterbenz)
        float l1 = f[2 * i + 1] - __bfloat162float(h1);
        __nv_bfloat162 hp = __halves2bfloat162(h0, h1);
        __nv_bfloat162 lp = __halves2bfloat162(__float2bfloat16(l0), __float2bfloat16(l1));
        hu[i] = *(uint32_t*)&hp;
        lu[i] = *(uint32_t*)&lp;
    }
    hi = make_uint4(hu[0], hu[1], hu[2], hu[3]);
    lo = make_uint4(lu[0], lu[1], lu[2], lu[3]);
}

__device__ __forceinline__ void ldm4(uint32_t* r, uint32_t addr) {
    asm volatile("ldmatrix.sync.aligned.m8n8.x4.shared.b16 {%0,%1,%2,%3}, [%4];"
                 : "=r"(r[0]), "=r"(r[1]), "=r"(r[2]), "=r"(r[3]) : "r"(addr));
}

__device__ __forceinline__ void mma16816(float* d, const uint32_t* a, uint32_t b0, uint32_t b1) {
    asm volatile(
        "mma.sync.aligned.m16n8k16.row.col.f32.bf16.bf16.f32 "
        "{%0,%1,%2,%3}, {%4,%5,%6,%7}, {%8,%9}, {%0,%1,%2,%3};"
        : "+f"(d[0]), "+f"(d[1]), "+f"(d[2]), "+f"(d[3])
        : "r"(a[0]), "r"(a[1]), "r"(a[2]), "r"(a[3]), "r"(b0), "r"(b1));
}

// ---------------- W conversion: W[k][n] fp32 -> Wt[n][k] bf16 hi/lo -------
__global__ __launch_bounds__(256) void conv_w(
    const float* __restrict__ Wq, const float* __restrict__ Wk,
    const float* __restrict__ Wv, const float* __restrict__ Wo)
{
    const float* W = (blockIdx.x == 0) ? Wq : (blockIdx.x == 1) ? Wk
                    : (blockIdx.x == 2) ? Wv : Wo;
    int t = threadIdx.x;
    int nr = t >> 1, half = t & 1;
#pragma unroll
    for (int j = 0; j < 8; j++) {
        int col8 = half * 8 + j;   // k-group (8 k's)
        int k0 = col8 * 8;
        float f[8];
#pragma unroll
        for (int i = 0; i < 8; i++) f[i] = W[(size_t)(k0 + i) * DIM + nr];
        uint4 hi, lo;
        pack8(f, hi, lo);
        g_bhi[blockIdx.x * 2048 + nr * 16 + col8] = hi;
        g_blo[blockIdx.x * 2048 + nr * 16 + col8] = lo;
    }
}

// ---------------- fused tensor-core GEMM ----------------------------------
// Loads/packs the A tile ONCE, then loops over nw weight matrices.
// split-bf16 via mma.sync: D = Ah*Bh + Ah*Bl + Al*Bh (fp32 accumulate)
// CTA: 128 rows x 128 cols, 512 threads, 16 warps in 4x4, warp tile 32x32
// Output: widx 0 -> g_qv q-halves (fp16), widx 1 -> g_k (fp32),
//         widx 2 -> g_qv v-halves (fp16), wbase 3 -> Yext (fp32)
#define SM_BYTES (4 * 128 * ASTR * 2)

__global__ __launch_bounds__(512) void fused_gemm(
    const float* __restrict__ Xext,
    const float* __restrict__ b0, const float* __restrict__ b1,
    const float* __restrict__ b2, float* __restrict__ Yext,
    int wbase, int nw, int n, float s0, float s1, float s2)
{
    extern __shared__ __align__(16) char smem[];
    __nv_bfloat16* Ah = (__nv_bfloat16*)smem;            // [128][ASTR]
    __nv_bfloat16* Al = Ah + 128 * ASTR;
    __nv_bfloat16* Bh = Al + 128 * ASTR;                 // Wt rows = n, cols = k
    __nv_bfloat16* Bl = Bh + 128 * ASTR;
    const uint32_t HL_OFF = 128 * ASTR * 2;              // hi -> lo byte offset

    const float* X = (wbase == 3) ? g_agg : Xext;

    int tid = threadIdx.x;
    int row0 = blockIdx.x * 128;

    // ---- stage A (once): load fp32 X tile, split to bf16 hi/lo in SMEM ----
    {
        int r = tid >> 2, quarter = tid & 3;
        int grow = row0 + r;
#pragma unroll
        for (int j = 0; j < 4; j++) {
            int c0 = quarter * 32 + j * 8;
            float f[8] = {0, 0, 0, 0, 0, 0, 0, 0};
            if (grow < n) {
                float4 a = *(const float4*)&X[(size_t)grow * DIM + c0];
                float4 b = *(const float4*)&X[(size_t)grow * DIM + c0 + 4];
                f[0] = a.x; f[1] = a.y; f[2] = a.z; f[3] = a.w;
                f[4] = b.x; f[5] = b.y; f[6] = b.z; f[7] = b.w;
            }
            uint4 hi, lo;
            pack8(f, hi, lo);
            *(uint4*)&Ah[r * ASTR + c0] = hi;
            *(uint4*)&Al[r * ASTR + c0] = lo;
        }
    }
    __syncthreads();

    int wid = tid >> 5, lane = tid & 31;
    int wm = wid & 3, wn = wid >> 2;          // 4x4 warp grid, warp tile 32x32
    uint32_t aBase = smem_u32(Ah);
    uint32_t bBase = smem_u32(Bh);

    for (int m = 0; m < nw; m++) {
        int widx = wbase + m;
        const float* bias = (m == 0) ? b0 : (m == 1) ? b1 : b2;
        float scale = (m == 0) ? s0 : (m == 1) ? s1 : s2;
        int toHalf = (wbase == 0) && (widx != 1);
        int qvOff = (widx == 0) ? 0 : 4;      // q halves at +0, v halves at +4
        float* Yf = (wbase == 3) ? Yext : g_k;
        __half* QV = (__half*)g_qv;

        // ---- load B for this weight set ----
        {
            const uint4* bh = g_bhi + widx * 2048;
            const uint4* bl = g_blo + widx * 2048;
#pragma unroll
            for (int i = 0; i < 4; i++) {
                int idx = tid * 4 + i;            // 0..2047
                int nrow = idx >> 4, c8 = idx & 15;
                *(uint4*)&Bh[nrow * ASTR + c8 * 8] = bh[idx];
                *(uint4*)&Bl[nrow * ASTR + c8 * 8] = bl[idx];
            }
        }
        __syncthreads();

        float acc[2][4][4];
#pragma unroll
        for (int mt = 0; mt < 2; mt++)
#pragma unroll
            for (int nt = 0; nt < 4; nt++)
#pragma unroll
                for (int i = 0; i < 4; i++) acc[mt][nt][i] = 0.0f;

#pragma unroll
        for (int ks = 0; ks < 8; ks++) {
            uint32_t a_h[2][4], a_l[2][4];
#pragma unroll
            for (int mt = 0; mt < 2; mt++) {
                int arow = wm * 32 + mt * 16 + (lane & 15);
                int acol = ks * 16 + (lane >> 4) * 8;
                uint32_t ad = aBase + (uint32_t)(arow * ASTR + acol) * 2;
                ldm4(a_h[mt], ad);
                ldm4(a_l[mt], ad + HL_OFF);
            }
            uint32_t b_h[2][4], b_l[2][4];
#pragma unroll
            for (int np = 0; np < 2; np++) {
                int brow = wn * 32 + np * 16 + (lane >> 4) * 8 + (lane & 7);
                int bcol = ks * 16 + ((lane >> 3) & 1) * 8;
                uint32_t bd = bBase + (uint32_t)(brow * ASTR + bcol) * 2;
                ldm4(b_h[np], bd);
                ldm4(b_l[np], bd + HL_OFF);
            }
#pragma unroll
            for (int mt = 0; mt < 2; mt++)
#pragma unroll
                for (int nt = 0; nt < 4; nt++) {
                    int np = nt >> 1, sel = (nt & 1) * 2;
                    mma16816(acc[mt][nt], a_h[mt], b_h[np][sel], b_h[np][sel + 1]);
                    mma16816(acc[mt][nt], a_h[mt], b_l[np][sel], b_l[np][sel + 1]);
                    mma16816(acc[mt][nt], a_l[mt], b_h[np][sel], b_h[np][sel + 1]);
                }
        }
        __syncthreads();   // all warps done reading B before next overwrite

        // ---- epilogue ----
#pragma unroll
        for (int mt = 0; mt < 2; mt++) {
            int rbase = row0 + wm * 32 + mt * 16 + (lane >> 2);
#pragma unroll
            for (int nt = 0; nt < 4; nt++) {
                int col = wn * 32 + nt * 8 + (lane & 3) * 2;
                float2 bv = *(const float2*)&bias[col];
                float x0 = (acc[mt][nt][0] + bv.x) * scale;
                float y0 = (acc[mt][nt][1] + bv.y) * scale;
                float x1 = (acc[mt][nt][2] + bv.x) * scale;
                float y1 = (acc[mt][nt][3] + bv.y) * scale;
                if (toHalf) {
                    // interleaved qv layout: half idx = node*256 + (col>>2)*8 + qvOff + (col&3)
                    uint32_t hoff = (uint32_t)((col >> 2) * 8 + qvOff + (col & 3));
                    if (rbase < n)
                        *(__half2*)&QV[(size_t)rbase * 256 + hoff] = __floats2half2_rn(x0, y0);
                    if (rbase + 8 < n)
                        *(__half2*)&QV[(size_t)(rbase + 8) * 256 + hoff] = __floats2half2_rn(x1, y1);
                } else {
                    if (rbase < n)
                        *(float2*)&Yf[(size_t)rbase * DIM + col] = make_float2(x0, y0);
                    if (rbase + 8 < n)
                        *(float2*)&Yf[(size_t)(rbase + 8) * DIM + col] = make_float2(x1, y1);
                }
            }
        }
    }
}

// ---------------- counting sort of edges by dst ---------------------------
__global__ void zero_counts(int n) {
    int i = blockIdx.x * blockDim.x + threadIdx.x;
    int stride = gridDim.x * blockDim.x;
    for (int j = i; j < n; j += stride) { g_cnt[j] = 0; g_fill[j] = 0; }
}

__global__ void hist_kernel(const int* __restrict__ dst, int E) {
    int i = blockIdx.x * blockDim.x + threadIdx.x;
    int stride = gridDim.x * blockDim.x;
    for (int e = i; e < E; e += stride) atomicAdd(&g_cnt[dst[e]], 1);
}

__global__ __launch_bounds__(256) void scan_blocks(int n) {
    __shared__ int s[256];
    int t = threadIdx.x;
    int gi = blockIdx.x * 256 + t;
    int v = (gi < n) ? g_cnt[gi] : 0;
    s[t] = v;
    __syncthreads();
#pragma unroll
    for (int off = 1; off < 256; off <<= 1) {
        int tmp = (t >= off) ? s[t - off] : 0;
        __syncthreads();
        s[t] += tmp;
        __syncthreads();
    }
    if (gi < n) g_start[gi] = s[t] - v;
    if (t == 255) g_bsum[blockIdx.x] = s[255];
}

__global__ __launch_bounds__(NB_MAX) void scan_bsums(int nb) {
    __shared__ int s[NB_MAX];
    int t = threadIdx.x;
    int v = (t < nb) ? g_bsum[t] : 0;
    s[t] = v;
    __syncthreads();
#pragma unroll
    for (int off = 1; off < NB_MAX; off <<= 1) {
        int tmp = (t >= off) ? s[t - off] : 0;
        __syncthreads();
        s[t] += tmp;
        __syncthreads();
    }
    if (t < nb) g_boff[t] = s[t] - v;
}

__global__ void add_offsets(int n) {
    int i = blockIdx.x * blockDim.x + threadIdx.x;
    int stride = gridDim.x * blockDim.x;
    for (int j = i; j < n; j += stride) g_start[j] += g_boff[j >> 8];
}

__global__ void scatter_kernel(const int* __restrict__ src,
                               const int* __restrict__ dst, int E) {
    int i = blockIdx.x * blockDim.x + threadIdx.x;
    int stride = gridDim.x * blockDim.x;
    for (int e = i; e < E; e += stride) {
        int d = dst[e];
        int pos = g_start[d] + atomicAdd(&g_fill[d], 1);
        g_esrc[pos] = src[e];
    }
}

// ---------------- attention: persistent strided warps ---------------------
// One resident wave; each warp grid-strides over nodes (load balance).
// Per edge: ONE LDG.128/lane gets q(4 halves)+v(4 halves) of the src node.
__global__ __launch_bounds__(256) void edge_sorted(int n) {
    int gw = (int)((blockIdx.x * blockDim.x + threadIdx.x) >> 5);
    int nwarps = (int)((gridDim.x * blockDim.x) >> 5);
    int lane = threadIdx.x & 31;

    for (int d = gw; d < n; d += nwarps) {
        int base = g_start[d];
        int deg  = g_cnt[d];

        float4 kv = *(const float4*)&g_k[(size_t)d * DIM + lane * 4];
        float4 agg = make_float4(0.f, 0.f, 0.f, 0.f);
        float zacc = 0.0f;

        for (int chunk = 0; chunk < deg; chunk += 32) {
            int nmax = min(32, deg - chunk);
            int sv = (chunk + lane < deg) ? g_esrc[base + chunk + lane] : 0;
#pragma unroll 2
            for (int t = 0; t < nmax; t++) {
                int s = __shfl_sync(0xffffffffu, sv, t);
                uint4 qv = g_qv[(size_t)s * 32 + lane];
                float2 q01 = __half22float2(*(__half2*)&qv.x);
                float2 q23 = __half22float2(*(__half2*)&qv.y);
                float p = q01.x * kv.x + q01.y * kv.y + q23.x * kv.z + q23.y * kv.w;
                p += __shfl_xor_sync(0xffffffffu, p, 1);
                p += __shfl_xor_sync(0xffffffffu, p, 2);
                float w = __expf(p);   // k pre-scaled; scores ~N(0,1), no overflow
                float2 v01 = __half22float2(*(__half2*)&qv.z);
                float2 v23 = __half22float2(*(__half2*)&qv.w);
                agg.x += w * v01.x; agg.y += w * v01.y;
                agg.z += w * v23.x; agg.w += w * v23.y;
                zacc += w;
            }
        }

        float4 o = make_float4(0.f, 0.f, 0.f, 0.f);
        if (deg > 0) {
            float zinv = 1.0f / zacc;
            o.x = agg.x * zinv; o.y = agg.y * zinv;
            o.z = agg.z * zinv; o.w = agg.w * zinv;
        }
        *(float4*)&g_agg[(size_t)d * DIM + lane * 4] = o;
    }
}

// ---------------- host entry ----------------------------------------------
extern "C" void kernel_launch(void* const* d_in, const int* in_sizes, int n_in,
                              void* d_out, int out_size)
{
    const float* x   = (const float*)d_in[0];
    const int*   src = (const int*)d_in[1];
    const int*   dst = (const int*)d_in[2];
    const float* Wq  = (const float*)d_in[3];
    const float* bq  = (const float*)d_in[4];
    const float* Wk  = (const float*)d_in[5];
    const float* bk  = (const float*)d_in[6];
    const float* Wv  = (const float*)d_in[7];
    const float* bv  = (const float*)d_in[8];
    const float* Wo  = (const float*)d_in[9];
    const float* bo  = (const float*)d_in[10];
    float* out = (float*)d_out;

    int n = in_sizes[0] / DIM;
    int E = in_sizes[1];
    int nb = (n + 255) / 256;
    int tiles = (n + 127) / 128;

    cudaFuncSetAttribute(fused_gemm, cudaFuncAttributeMaxDynamicSharedMemorySize, SM_BYTES);

    const float inv_sqrt_hd = 0.25f;  // 1/sqrt(16)

    // Fork a side stream for the edge sort (independent of the GEMMs).
    cudaStream_t s2;
    cudaStreamCreateWithFlags(&s2, cudaStreamNonBlocking);
    cudaEvent_t eFork, eJoin;
    cudaEventCreateWithFlags(&eFork, cudaEventDisableTiming);
    cudaEventCreateWithFlags(&eJoin, cudaEventDisableTiming);

    cudaEventRecord(eFork, 0);
    cudaStreamWaitEvent(s2, eFork, 0);

    // ---- side stream: counting sort of edges by dst (hidden under GEMM) ----
    zero_counts<<<256, 256, 0, s2>>>(n);
    hist_kernel<<<1024, 256, 0, s2>>>(dst, E);
    scan_blocks<<<nb, 256, 0, s2>>>(n);
    scan_bsums<<<1, NB_MAX, 0, s2>>>(nb);
    add_offsets<<<256, 256, 0, s2>>>(n);
    scatter_kernel<<<1024, 256, 0, s2>>>(src, dst, E);
    cudaEventRecord(eJoin, s2);

    // ---- main stream: W conversion + fused q/k/v projection ----
    conv_w<<<4, 256>>>(Wq, Wk, Wv, Wo);
    fused_gemm<<<tiles, 512, SM_BYTES>>>(x, bq, bk, bv, nullptr, 0, 3, n,
                                         1.0f, inv_sqrt_hd, 1.0f);

    // join: attention needs both the sorted edges and q/k/v
    cudaStreamWaitEvent(0, eJoin, 0);
    edge_sorted<<<888, 256>>>(n);   // ~one resident wave of persistent warps

    // output projection
    fused_gemm<<<tiles, 512, SM_BYTES>>>(nullptr, bo, bo, bo, out, 3, 1, n,
                                         1.0f, 1.0f, 1.0f);
}